// round 2
// baseline (speedup 1.0000x reference)
#include <cuda_runtime.h>
#include <cuda_bf16.h>

#define BATCH 32
#define SEQ   512
#define DIM   1024
#define HID   1024

// ---------------- scratch (device globals; no cudaMalloc allowed) ----------
__device__ float g_xu[(size_t)SEQ * BATCH * 4 * HID];  // [s][b][gate][j], 256MB
__device__ float g_hT[2][HID * BATCH];                 // transposed h: [k][b]
__device__ float g_c[BATCH * HID];                     // c state [b][j]

// ---------------- packed f32x2 helpers -------------------------------------
__device__ __forceinline__ unsigned long long pack2(float a, float b) {
    unsigned long long r;
    asm("mov.b64 %0, {%1, %2};" : "=l"(r) : "f"(a), "f"(b));
    return r;
}
__device__ __forceinline__ unsigned long long fma2(unsigned long long a,
                                                   unsigned long long b,
                                                   unsigned long long c) {
    unsigned long long d;
    asm("fma.rn.f32x2 %0, %1, %2, %3;" : "=l"(d) : "l"(a), "l"(b), "l"(c));
    return d;
}
__device__ __forceinline__ float2 unpack2(unsigned long long v) {
    float2 r;
    asm("mov.b64 {%0, %1}, %2;" : "=f"(r.x), "=f"(r.y) : "l"(v));
    return r;
}

__device__ __forceinline__ float sigmoidf_(float x) {
    return 1.0f / (1.0f + __expf(-x));
}

// ---------------------------------------------------------------------------
// init: g_c = c0 ; g_hT[0][k][b] = h0[b][k]
// ---------------------------------------------------------------------------
__global__ void init_state(const float* __restrict__ h0,
                           const float* __restrict__ c0) {
    int idx = blockIdx.x * 256 + threadIdx.x;   // 0 .. 32767
    int b = idx >> 10;
    int k = idx & 1023;
    g_c[idx] = c0[idx];
    g_hT[0][k * BATCH + b] = h0[idx];
}

// ---------------------------------------------------------------------------
// Phase 1: g_xu[s][b][g][j] = sum_k x[b][s][k] * U_g[k][j] + b_g[j]
// M = 16384 (m = b*512+s), per-gate N = 1024, K = 1024.
// Tile 128(M) x 128(N) x 32(K), 256 threads, 8x8 per thread (f32x2 packed).
// ---------------------------------------------------------------------------
__global__ __launch_bounds__(256) void xu_gemm(
    const float* __restrict__ x,
    const float* __restrict__ Ui, const float* __restrict__ Uf,
    const float* __restrict__ Uc, const float* __restrict__ Uo,
    const float* __restrict__ bi, const float* __restrict__ bf,
    const float* __restrict__ bc, const float* __restrict__ bo)
{
    __shared__ float As[32 * 132];   // [k][m] transposed, padded (16B-aligned rows)
    __shared__ float Bs[32 * 132];   // [k][j]

    const int tid  = threadIdx.x;
    const int m0   = blockIdx.x * 128;
    const int by   = blockIdx.y;          // 0..31
    const int gate = by >> 3;
    const int j0   = (by & 7) * 128;

    const float* U    = (gate == 0) ? Ui : (gate == 1) ? Uf : (gate == 2) ? Uc : Uo;
    const float* bias = (gate == 0) ? bi : (gate == 1) ? bf : (gate == 2) ? bc : bo;

    const int tn = tid & 15;   // 16 j-groups of 8
    const int tm = tid >> 4;   // 16 m-groups of 8

    unsigned long long acc2[8][4];
    #pragma unroll
    for (int i = 0; i < 8; i++)
        #pragma unroll
        for (int j = 0; j < 4; j++) acc2[i][j] = 0ULL;

    for (int k0 = 0; k0 < DIM; k0 += 32) {
        // x tile: 128 m x 32 k  -> As[k][m]
        #pragma unroll
        for (int r = 0; r < 4; ++r) {
            int f4  = tid + 256 * r;           // 0..1023 float4 slots
            int row = f4 >> 3;                 // m row 0..127
            int c4  = f4 & 7;                  // k float4 col
            float4 v = *(const float4*)&x[(size_t)(m0 + row) * DIM + k0 + c4 * 4];
            As[(c4 * 4 + 0) * 132 + row] = v.x;
            As[(c4 * 4 + 1) * 132 + row] = v.y;
            As[(c4 * 4 + 2) * 132 + row] = v.z;
            As[(c4 * 4 + 3) * 132 + row] = v.w;
        }
        // U tile: 32 k x 128 j -> Bs[k][j]
        #pragma unroll
        for (int r = 0; r < 4; ++r) {
            int f4  = tid + 256 * r;           // 0..1023
            int row = f4 >> 5;                 // k row 0..31
            int c4  = f4 & 31;                 // j float4 col
            *(float4*)&Bs[row * 132 + c4 * 4] =
                *(const float4*)&U[(size_t)(k0 + row) * HID + j0 + c4 * 4];
        }
        __syncthreads();

        #pragma unroll 8
        for (int kk = 0; kk < 32; ++kk) {
            float4 a0 = *(const float4*)&As[kk * 132 + tm * 8];
            float4 a1 = *(const float4*)&As[kk * 132 + tm * 8 + 4];
            ulonglong2 b0 = *(const ulonglong2*)&Bs[kk * 132 + tn * 8];
            ulonglong2 b1 = *(const ulonglong2*)&Bs[kk * 132 + tn * 8 + 4];
            unsigned long long bv[4] = {b0.x, b0.y, b1.x, b1.y};
            float av[8] = {a0.x, a0.y, a0.z, a0.w, a1.x, a1.y, a1.z, a1.w};
            #pragma unroll
            for (int i = 0; i < 8; i++) {
                unsigned long long aa = pack2(av[i], av[i]);
                #pragma unroll
                for (int jp = 0; jp < 4; jp++)
                    acc2[i][jp] = fma2(aa, bv[jp], acc2[i][jp]);
            }
        }
        __syncthreads();
    }

    float bv[8];
    #pragma unroll
    for (int j = 0; j < 8; j++) bv[j] = bias[j0 + tn * 8 + j];

    #pragma unroll
    for (int i = 0; i < 8; i++) {
        int m  = m0 + tm * 8 + i;
        int b_ = m >> 9;          // batch
        int s_ = m & 511;         // seq
        float* dst = &g_xu[(((size_t)s_ * BATCH + b_) * 4 + gate) * HID + j0 + tn * 8];
        float2 p0 = unpack2(acc2[i][0]);
        float2 p1 = unpack2(acc2[i][1]);
        float2 p2 = unpack2(acc2[i][2]);
        float2 p3 = unpack2(acc2[i][3]);
        float4 r0 = make_float4(p0.x + bv[0], p0.y + bv[1], p1.x + bv[2], p1.y + bv[3]);
        float4 r1 = make_float4(p2.x + bv[4], p2.y + bv[5], p3.x + bv[6], p3.y + bv[7]);
        *(float4*)&dst[0] = r0;
        *(float4*)&dst[4] = r1;
    }
}

// ---------------------------------------------------------------------------
// Phase 2: one step of the recurrence.
//   z_g[b][j] = xu[s][b][g][j] + sum_k h[b][k] * V_g[k][j]   (g = i,f,c,o)
//   gating -> c, h ; writes h into hT[next parity], out, and g_c.
// Grid: 128 CTAs x 256 threads. CTA covers 8 hidden columns x 4 gates x 32 b.
// Thread = (1 batch, 1 column, all 4 gates). V and hT staged via smem chunks.
// ---------------------------------------------------------------------------
__global__ __launch_bounds__(256) void lstm_step(
    const float* __restrict__ Vi, const float* __restrict__ Vf,
    const float* __restrict__ Vc, const float* __restrict__ Vo,
    float* __restrict__ out_hs,   // [B][S][H]
    float* __restrict__ out_ht,   // [B][H]
    float* __restrict__ out_ct,   // [B][H]
    int s, int par)
{
    __shared__ float Vt[128 * 8 * 4];   // [kk][j][gate] interleaved, 16KB
    __shared__ float Ht[128 * 32];      // [kk][b], 16KB

    const int tid = threadIdx.x;
    const int j   = tid & 7;            // local column
    const int m   = tid >> 3;           // batch 0..31
    const int jb  = blockIdx.x * 8;     // column base
    const int jg  = jb + j;             // global hidden column

    const float* __restrict__ hT = g_hT[par];

    // z accumulators start from precomputed xu + bias
    const size_t xu_base = (((size_t)s * BATCH + m) * 4) * HID + jg;
    float zi = g_xu[xu_base + 0 * HID];
    float zf = g_xu[xu_base + 1 * HID];
    float zg = g_xu[xu_base + 2 * HID];
    float zo = g_xu[xu_base + 3 * HID];

    for (int k0 = 0; k0 < HID; k0 += 128) {
        // stage hT chunk: [128][32] contiguous copy
        #pragma unroll
        for (int t = 0; t < 16; ++t) {
            int idx = tid + t * 256;
            Ht[idx] = hT[k0 * 32 + idx];
        }
        // stage V chunk for 4 gates, interleaved [kk][j][g]
        #pragma unroll
        for (int t = 0; t < 4; ++t) {
            int e   = tid + t * 256;    // 0..1023
            int row = e >> 3;
            int col = e & 7;
            float* vd = &Vt[(row * 8 + col) * 4];
            vd[0] = Vi[(size_t)(k0 + row) * HID + jb + col];
            vd[1] = Vf[(size_t)(k0 + row) * HID + jb + col];
            vd[2] = Vc[(size_t)(k0 + row) * HID + jb + col];
            vd[3] = Vo[(size_t)(k0 + row) * HID + jb + col];
        }
        __syncthreads();

        #pragma unroll 8
        for (int kk = 0; kk < 128; ++kk) {
            float h  = Ht[kk * 32 + m];
            float4 v = *(const float4*)&Vt[(kk * 8 + j) * 4];
            zi = fmaf(h, v.x, zi);
            zf = fmaf(h, v.y, zf);
            zg = fmaf(h, v.z, zg);
            zo = fmaf(h, v.w, zo);
        }
        __syncthreads();
    }

    // gating
    float ig = sigmoidf_(zi);
    float fg = sigmoidf_(zf);
    float gg = tanhf(zg);
    float og = sigmoidf_(zo);

    int ci = m * HID + jg;
    float c = fg * g_c[ci] + ig * gg;
    float h = og * tanhf(c);
    g_c[ci] = c;

    g_hT[1 - par][jg * BATCH + m] = h;
    out_hs[((size_t)m * SEQ + s) * HID + jg] = h;
    if (s == SEQ - 1) {
        out_ht[ci] = h;
        out_ct[ci] = c;
    }
}

// ---------------------------------------------------------------------------
extern "C" void kernel_launch(void* const* d_in, const int* in_sizes, int n_in,
                              void* d_out, int out_size) {
    const float* x   = (const float*)d_in[0];
    const float* h0  = (const float*)d_in[1];
    const float* c0  = (const float*)d_in[2];
    const float* U_i = (const float*)d_in[3];
    const float* V_i = (const float*)d_in[4];
    const float* b_i = (const float*)d_in[5];
    const float* U_f = (const float*)d_in[6];
    const float* V_f = (const float*)d_in[7];
    const float* b_f = (const float*)d_in[8];
    const float* U_c = (const float*)d_in[9];
    const float* V_c = (const float*)d_in[10];
    const float* b_c = (const float*)d_in[11];
    const float* U_o = (const float*)d_in[12];
    const float* V_o = (const float*)d_in[13];
    const float* b_o = (const float*)d_in[14];

    float* out    = (float*)d_out;
    float* out_hs = out;                                   // [B][S][H]
    float* out_ht = out + (size_t)BATCH * SEQ * HID;       // [B][H]
    float* out_ct = out_ht + (size_t)BATCH * HID;          // [B][H]

    init_state<<<128, 256>>>(h0, c0);

    dim3 g1(128, 32);
    xu_gemm<<<g1, 256>>>(x, U_i, U_f, U_c, U_o, b_i, b_f, b_c, b_o);

    for (int s = 0; s < SEQ; ++s) {
        lstm_step<<<128, 256>>>(V_i, V_f, V_c, V_o,
                                out_hs, out_ht, out_ct, s, s & 1);
    }
}

// round 3
// speedup vs baseline: 1.3721x; 1.3721x over previous
#include <cuda_runtime.h>
#include <cuda_bf16.h>

#define BATCH 32
#define SEQ   512
#define DIM   1024
#define HID   1024
#define NCTA  128
#define KCH   256   // h chunk (k elements) staged per inner block

// ---------------- scratch (device globals; no cudaMalloc allowed) ----------
__device__ float g_xu[(size_t)SEQ * BATCH * 4 * HID];  // [s][b][gate][j]
__device__ float g_h[2][BATCH * HID];                  // h double buffer [par][b][k]
__device__ unsigned g_bar;                             // global barrier counter

// ---------------- packed f32x2 helpers -------------------------------------
__device__ __forceinline__ unsigned long long pack2(float a, float b) {
    unsigned long long r;
    asm("mov.b64 %0, {%1, %2};" : "=l"(r) : "f"(a), "f"(b));
    return r;
}
__device__ __forceinline__ unsigned long long fma2(unsigned long long a,
                                                   unsigned long long b,
                                                   unsigned long long c) {
    unsigned long long d;
    asm("fma.rn.f32x2 %0, %1, %2, %3;" : "=l"(d) : "l"(a), "l"(b), "l"(c));
    return d;
}
__device__ __forceinline__ float2 unpack2(unsigned long long v) {
    float2 r;
    asm("mov.b64 {%0, %1}, %2;" : "=f"(r.x), "=f"(r.y) : "l"(v));
    return r;
}
__device__ __forceinline__ float sigmoidf_(float x) {
    return 1.0f / (1.0f + __expf(-x));
}

// ---------------------------------------------------------------------------
// init: g_h[0][b][k] = h0[b][k] (same layout: plain copy); reset barrier.
// ---------------------------------------------------------------------------
__global__ void init_state(const float* __restrict__ h0) {
    int idx = blockIdx.x * 256 + threadIdx.x;   // 0 .. 32767
    g_h[0][idx] = h0[idx];
    if (idx == 0) g_bar = 0;
}

// ---------------------------------------------------------------------------
// Phase 1: g_xu[s][b][g][j] = sum_k x[b][s][k] * U_g[k][j] + b_g[j]
// Tile 128(M) x 128(N) x 32(K), 256 threads, 8x8 per thread (f32x2 packed).
// ---------------------------------------------------------------------------
__global__ __launch_bounds__(256) void xu_gemm(
    const float* __restrict__ x,
    const float* __restrict__ Ui, const float* __restrict__ Uf,
    const float* __restrict__ Uc, const float* __restrict__ Uo,
    const float* __restrict__ bi, const float* __restrict__ bf,
    const float* __restrict__ bc, const float* __restrict__ bo)
{
    __shared__ float As[32 * 132];   // [k][m] transposed, padded
    __shared__ float Bs[32 * 132];   // [k][j]

    const int tid  = threadIdx.x;
    const int m0   = blockIdx.x * 128;
    const int by   = blockIdx.y;          // 0..31
    const int gate = by >> 3;
    const int j0   = (by & 7) * 128;

    const float* U    = (gate == 0) ? Ui : (gate == 1) ? Uf : (gate == 2) ? Uc : Uo;
    const float* bias = (gate == 0) ? bi : (gate == 1) ? bf : (gate == 2) ? bc : bo;

    const int tn = tid & 15;
    const int tm = tid >> 4;

    unsigned long long acc2[8][4];
    #pragma unroll
    for (int i = 0; i < 8; i++)
        #pragma unroll
        for (int j = 0; j < 4; j++) acc2[i][j] = 0ULL;

    for (int k0 = 0; k0 < DIM; k0 += 32) {
        #pragma unroll
        for (int r = 0; r < 4; ++r) {
            int f4  = tid + 256 * r;
            int row = f4 >> 3;
            int c4  = f4 & 7;
            float4 v = *(const float4*)&x[(size_t)(m0 + row) * DIM + k0 + c4 * 4];
            As[(c4 * 4 + 0) * 132 + row] = v.x;
            As[(c4 * 4 + 1) * 132 + row] = v.y;
            As[(c4 * 4 + 2) * 132 + row] = v.z;
            As[(c4 * 4 + 3) * 132 + row] = v.w;
        }
        #pragma unroll
        for (int r = 0; r < 4; ++r) {
            int f4  = tid + 256 * r;
            int row = f4 >> 5;
            int c4  = f4 & 31;
            *(float4*)&Bs[row * 132 + c4 * 4] =
                *(const float4*)&U[(size_t)(k0 + row) * HID + j0 + c4 * 4];
        }
        __syncthreads();

        #pragma unroll 8
        for (int kk = 0; kk < 32; ++kk) {
            float4 a0 = *(const float4*)&As[kk * 132 + tm * 8];
            float4 a1 = *(const float4*)&As[kk * 132 + tm * 8 + 4];
            ulonglong2 b0 = *(const ulonglong2*)&Bs[kk * 132 + tn * 8];
            ulonglong2 b1 = *(const ulonglong2*)&Bs[kk * 132 + tn * 8 + 4];
            unsigned long long bv[4] = {b0.x, b0.y, b1.x, b1.y};
            float av[8] = {a0.x, a0.y, a0.z, a0.w, a1.x, a1.y, a1.z, a1.w};
            #pragma unroll
            for (int i = 0; i < 8; i++) {
                unsigned long long aa = pack2(av[i], av[i]);
                #pragma unroll
                for (int jp = 0; jp < 4; jp++)
                    acc2[i][jp] = fma2(aa, bv[jp], acc2[i][jp]);
            }
        }
        __syncthreads();
    }

    float bv[8];
    #pragma unroll
    for (int j = 0; j < 8; j++) bv[j] = bias[j0 + tn * 8 + j];

    #pragma unroll
    for (int i = 0; i < 8; i++) {
        int m  = m0 + tm * 8 + i;
        int b_ = m >> 9;
        int s_ = m & 511;
        float* dst = &g_xu[(((size_t)s_ * BATCH + b_) * 4 + gate) * HID + j0 + tn * 8];
        float2 p0 = unpack2(acc2[i][0]);
        float2 p1 = unpack2(acc2[i][1]);
        float2 p2 = unpack2(acc2[i][2]);
        float2 p3 = unpack2(acc2[i][3]);
        float4 r0 = make_float4(p0.x + bv[0], p0.y + bv[1], p1.x + bv[2], p1.y + bv[3]);
        float4 r1 = make_float4(p2.x + bv[4], p2.y + bv[5], p3.x + bv[6], p3.y + bv[7]);
        *(float4*)&dst[0] = r0;
        *(float4*)&dst[4] = r1;
    }
}

// ---------------------------------------------------------------------------
// Phase 2: PERSISTENT recurrence kernel. One launch covers all 512 steps.
// 128 CTAs (1/SM, all resident), 256 threads: thread = (batch m, column j).
// V slice for this CTA's 8 columns x 4 gates lives in smem the whole time.
// Per step: stage h in 4 chunks (reg-prefetch pipelined), packed f32x2 FMA,
// gate math in registers (c state register-resident), global spin barrier.
// smem: Vs = 8 * 4100 floats (j-stride padded), Hs = 32 * 260 floats.
// ---------------------------------------------------------------------------
#define VS_JSTR 4100          // 4*1024 + 4 pad -> j step = 4 banks
#define HS_MSTR 260           // 256 + 4 pad   -> m step = 4 banks
#define SMEM_FLOATS (8 * VS_JSTR + 32 * HS_MSTR)

__global__ __launch_bounds__(256, 1) void lstm_persist(
    const float* __restrict__ Vi, const float* __restrict__ Vf,
    const float* __restrict__ Vc, const float* __restrict__ Vo,
    const float* __restrict__ c0,
    float* __restrict__ out_hs,   // [B][S][H]
    float* __restrict__ out_ht,   // [B][H]
    float* __restrict__ out_ct)   // [B][H]
{
    extern __shared__ float sm[];
    float* Vs = sm;                    // [j][g*1024 + k], row stride VS_JSTR
    float* Hs = sm + 8 * VS_JSTR;      // [m][k-chunk], row stride HS_MSTR

    const int tid = threadIdx.x;
    const int j   = tid & 7;
    const int m   = tid >> 3;
    const int jb  = blockIdx.x * 8;
    const int jg  = jb + j;

    // ---- one-time V load into smem (8 cols x 4 gates x 1024 k) ----
    for (int e = tid; e < 8 * 4 * 1024; e += 256) {
        int jj = e & 7;
        int k  = (e >> 3) & 1023;
        int g  = e >> 13;
        const float* Vg = (g == 0) ? Vi : (g == 1) ? Vf : (g == 2) ? Vc : Vo;
        Vs[jj * VS_JSTR + g * 1024 + k] = __ldg(&Vg[(size_t)k * HID + jb + jj]);
    }

    float cc = __ldg(&c0[m * HID + jg]);   // register-resident cell state
    float hlast = 0.f;

    for (int s = 0; s < SEQ; ++s) {
        const float* __restrict__ hsrc = g_h[s & 1];

        // xu for this (s, m, 4 gates, jg) — issued early, used at step end
        const float* xup = &g_xu[(((size_t)s * BATCH + m) * 4) * HID + jg];
        float xi = __ldcs(xup);
        float xf = __ldcs(xup + HID);
        float xg = __ldcs(xup + 2 * HID);
        float xo = __ldcs(xup + 3 * HID);

        unsigned long long a_i = 0, a_f = 0, a_c = 0, a_o = 0;

        // prefetch h chunk 0 into registers (ld.cg: bypass stale L1)
        float4 hreg[8];
        #pragma unroll
        for (int r = 0; r < 8; ++r) {
            int f  = tid + 256 * r;         // float4 index in chunk
            int b  = f >> 6;                // 64 float4 per 256-k row
            int kq = f & 63;
            hreg[r] = __ldcg((const float4*)&hsrc[b * HID + kq * 4]);
        }

        #pragma unroll
        for (int ch = 0; ch < HID / KCH; ++ch) {
            __syncthreads();               // previous chunk compute done
            #pragma unroll
            for (int r = 0; r < 8; ++r) {
                int f  = tid + 256 * r;
                int b  = f >> 6;
                int kq = f & 63;
                *(float4*)&Hs[b * HS_MSTR + kq * 4] = hreg[r];
            }
            __syncthreads();
            if (ch < HID / KCH - 1) {       // prefetch next chunk (overlaps compute)
                int k0n = (ch + 1) * KCH;
                #pragma unroll
                for (int r = 0; r < 8; ++r) {
                    int f  = tid + 256 * r;
                    int b  = f >> 6;
                    int kq = f & 63;
                    hreg[r] = __ldcg((const float4*)&hsrc[b * HID + k0n + kq * 4]);
                }
            }

            const float* vsj = &Vs[j * VS_JSTR + ch * KCH];
            const float* hsm = &Hs[m * HS_MSTR];
            #pragma unroll 8
            for (int kk = 0; kk < KCH; kk += 4) {
                ulonglong2 h2 = *(const ulonglong2*)&hsm[kk];
                ulonglong2 v;
                v = *(const ulonglong2*)&vsj[0 * 1024 + kk];
                a_i = fma2(h2.x, v.x, a_i); a_i = fma2(h2.y, v.y, a_i);
                v = *(const ulonglong2*)&vsj[1 * 1024 + kk];
                a_f = fma2(h2.x, v.x, a_f); a_f = fma2(h2.y, v.y, a_f);
                v = *(const ulonglong2*)&vsj[2 * 1024 + kk];
                a_c = fma2(h2.x, v.x, a_c); a_c = fma2(h2.y, v.y, a_c);
                v = *(const ulonglong2*)&vsj[3 * 1024 + kk];
                a_o = fma2(h2.x, v.x, a_o); a_o = fma2(h2.y, v.y, a_o);
            }
        }

        // gating (all in registers)
        float2 p;
        p = unpack2(a_i); float zi = xi + p.x + p.y;
        p = unpack2(a_f); float zf = xf + p.x + p.y;
        p = unpack2(a_c); float zg = xg + p.x + p.y;
        p = unpack2(a_o); float zo = xo + p.x + p.y;

        float ig = sigmoidf_(zi);
        float fg = sigmoidf_(zf);
        float gg = tanhf(zg);
        float og = sigmoidf_(zo);
        cc = fg * cc + ig * gg;
        float h = og * tanhf(cc);
        hlast = h;

        __stcg(&g_h[(s + 1) & 1][m * HID + jg], h);
        __stcs(&out_hs[((size_t)m * SEQ + s) * HID + jg], h);

        if (s < SEQ - 1) {
            __syncthreads();                       // all threads' h stores issued
            if (tid == 0) {
                __threadfence();                   // publish h before arriving
                atomicAdd(&g_bar, 1u);
                unsigned target = (unsigned)NCTA * (unsigned)(s + 1);
                unsigned v;
                do {
                    asm volatile("ld.acquire.gpu.u32 %0, [%1];"
                                 : "=r"(v) : "l"(&g_bar));
                } while (v < target);
            }
            __syncthreads();                       // release to whole CTA
        }
    }

    out_ht[m * HID + jg] = hlast;
    out_ct[m * HID + jg] = cc;
}

// ---------------------------------------------------------------------------
extern "C" void kernel_launch(void* const* d_in, const int* in_sizes, int n_in,
                              void* d_out, int out_size) {
    const float* x   = (const float*)d_in[0];
    const float* h0  = (const float*)d_in[1];
    const float* c0  = (const float*)d_in[2];
    const float* U_i = (const float*)d_in[3];
    const float* V_i = (const float*)d_in[4];
    const float* b_i = (const float*)d_in[5];
    const float* U_f = (const float*)d_in[6];
    const float* V_f = (const float*)d_in[7];
    const float* b_f = (const float*)d_in[8];
    const float* U_c = (const float*)d_in[9];
    const float* V_c = (const float*)d_in[10];
    const float* b_c = (const float*)d_in[11];
    const float* U_o = (const float*)d_in[12];
    const float* V_o = (const float*)d_in[13];
    const float* b_o = (const float*)d_in[14];

    float* out    = (float*)d_out;
    float* out_hs = out;                                   // [B][S][H]
    float* out_ht = out + (size_t)BATCH * SEQ * HID;       // [B][H]
    float* out_ct = out_ht + (size_t)BATCH * HID;          // [B][H]

    static_assert(SMEM_FLOATS * 4 <= 230000, "smem budget");
    cudaFuncSetAttribute(lstm_persist,
                         cudaFuncAttributeMaxDynamicSharedMemorySize,
                         SMEM_FLOATS * 4);

    init_state<<<128, 256>>>(h0);

    dim3 g1(128, 32);
    xu_gemm<<<g1, 256>>>(x, U_i, U_f, U_c, U_o, b_i, b_f, b_c, b_o);

    lstm_persist<<<NCTA, 256, SMEM_FLOATS * 4>>>(
        V_i, V_f, V_c, V_o, c0, out_hs, out_ht, out_ct);
}

// round 4
// speedup vs baseline: 1.3867x; 1.0106x over previous
#include <cuda_runtime.h>
#include <cuda_bf16.h>

#define BATCH 32
#define SEQ   512
#define DIM   1024
#define HID   1024
#define NCTA  128
#define NTH   512
#define KCH   256   // h chunk (k elements) per half per stage

// ---------------- scratch (device globals; no cudaMalloc allowed) ----------
__device__ float g_xu[(size_t)SEQ * BATCH * 4 * HID];  // [s][b][gate][j]
__device__ float g_h[2][BATCH * HID];                  // h double buffer [par][b][k]
__device__ unsigned g_bar;                             // global barrier counter

// ---------------- packed f32x2 helpers -------------------------------------
__device__ __forceinline__ unsigned long long pack2(float a, float b) {
    unsigned long long r;
    asm("mov.b64 %0, {%1, %2};" : "=l"(r) : "f"(a), "f"(b));
    return r;
}
__device__ __forceinline__ unsigned long long fma2(unsigned long long a,
                                                   unsigned long long b,
                                                   unsigned long long c) {
    unsigned long long d;
    asm("fma.rn.f32x2 %0, %1, %2, %3;" : "=l"(d) : "l"(a), "l"(b), "l"(c));
    return d;
}
__device__ __forceinline__ float2 unpack2(unsigned long long v) {
    float2 r;
    asm("mov.b64 {%0, %1}, %2;" : "=f"(r.x), "=f"(r.y) : "l"(v));
    return r;
}
__device__ __forceinline__ float sigmoidf_(float x) {
    return 1.0f / (1.0f + __expf(-x));
}

// ---------------------------------------------------------------------------
__global__ void init_state(const float* __restrict__ h0) {
    int idx = blockIdx.x * 256 + threadIdx.x;   // 0 .. 32767
    g_h[0][idx] = h0[idx];
    if (idx == 0) g_bar = 0;
}

// ---------------------------------------------------------------------------
// Phase 1: g_xu[s][b][g][j] = sum_k x[b][s][k] * U_g[k][j] + b_g[j]
// Tile 128(M) x 128(N) x 32(K), 256 threads, 8x8 per thread (f32x2 packed).
// ---------------------------------------------------------------------------
__global__ __launch_bounds__(256, 2) void xu_gemm(
    const float* __restrict__ x,
    const float* __restrict__ Ui, const float* __restrict__ Uf,
    const float* __restrict__ Uc, const float* __restrict__ Uo,
    const float* __restrict__ bi, const float* __restrict__ bf,
    const float* __restrict__ bc, const float* __restrict__ bo)
{
    __shared__ float As[32 * 132];   // [k][m] transposed, padded
    __shared__ float Bs[32 * 132];   // [k][j]

    const int tid  = threadIdx.x;
    const int m0   = blockIdx.x * 128;
    const int by   = blockIdx.y;          // 0..31
    const int gate = by >> 3;
    const int j0   = (by & 7) * 128;

    const float* U    = (gate == 0) ? Ui : (gate == 1) ? Uf : (gate == 2) ? Uc : Uo;
    const float* bias = (gate == 0) ? bi : (gate == 1) ? bf : (gate == 2) ? bc : bo;

    const int tn = tid & 15;
    const int tm = tid >> 4;

    unsigned long long acc2[8][4];
    #pragma unroll
    for (int i = 0; i < 8; i++)
        #pragma unroll
        for (int j = 0; j < 4; j++) acc2[i][j] = 0ULL;

    for (int k0 = 0; k0 < DIM; k0 += 32) {
        #pragma unroll
        for (int r = 0; r < 4; ++r) {
            int f4  = tid + 256 * r;
            int row = f4 >> 3;
            int c4  = f4 & 7;
            float4 v = *(const float4*)&x[(size_t)(m0 + row) * DIM + k0 + c4 * 4];
            As[(c4 * 4 + 0) * 132 + row] = v.x;
            As[(c4 * 4 + 1) * 132 + row] = v.y;
            As[(c4 * 4 + 2) * 132 + row] = v.z;
            As[(c4 * 4 + 3) * 132 + row] = v.w;
        }
        #pragma unroll
        for (int r = 0; r < 4; ++r) {
            int f4  = tid + 256 * r;
            int row = f4 >> 5;
            int c4  = f4 & 31;
            *(float4*)&Bs[row * 132 + c4 * 4] =
                *(const float4*)&U[(size_t)(k0 + row) * HID + j0 + c4 * 4];
        }
        __syncthreads();

        #pragma unroll 8
        for (int kk = 0; kk < 32; ++kk) {
            float4 a0 = *(const float4*)&As[kk * 132 + tm * 8];
            float4 a1 = *(const float4*)&As[kk * 132 + tm * 8 + 4];
            ulonglong2 b0 = *(const ulonglong2*)&Bs[kk * 132 + tn * 8];
            ulonglong2 b1 = *(const ulonglong2*)&Bs[kk * 132 + tn * 8 + 4];
            unsigned long long bv[4] = {b0.x, b0.y, b1.x, b1.y};
            float av[8] = {a0.x, a0.y, a0.z, a0.w, a1.x, a1.y, a1.z, a1.w};
            #pragma unroll
            for (int i = 0; i < 8; i++) {
                unsigned long long aa = pack2(av[i], av[i]);
                #pragma unroll
                for (int jp = 0; jp < 4; jp++)
                    acc2[i][jp] = fma2(aa, bv[jp], acc2[i][jp]);
            }
        }
        __syncthreads();
    }

    float bv[8];
    #pragma unroll
    for (int j = 0; j < 8; j++) bv[j] = bias[j0 + tn * 8 + j];

    #pragma unroll
    for (int i = 0; i < 8; i++) {
        int m  = m0 + tm * 8 + i;
        int b_ = m >> 9;
        int s_ = m & 511;
        float* dst = &g_xu[(((size_t)s_ * BATCH + b_) * 4 + gate) * HID + j0 + tn * 8];
        float2 p0 = unpack2(acc2[i][0]);
        float2 p1 = unpack2(acc2[i][1]);
        float2 p2 = unpack2(acc2[i][2]);
        float2 p3 = unpack2(acc2[i][3]);
        float4 r0 = make_float4(p0.x + bv[0], p0.y + bv[1], p1.x + bv[2], p1.y + bv[3]);
        float4 r1 = make_float4(p2.x + bv[4], p2.y + bv[5], p3.x + bv[6], p3.y + bv[7]);
        *(float4*)&dst[0] = r0;
        *(float4*)&dst[4] = r1;
    }
}

// ---------------------------------------------------------------------------
// Phase 2: PERSISTENT recurrence. 128 CTAs x 512 threads.
// thread = (k-half kh, batch m, column j); each thread: 4 gates x 512 k.
// V slice (8 cols x 4 gates x 1024 k = 128KB) stays in smem for all steps.
// Hs: 2 halves x 256-k chunk x 32 m, double-buffered via register prefetch.
// Halves reduced via smem; gating + state by half 0; global spin barrier.
// ---------------------------------------------------------------------------
#define VS_JSTR 4100          // 4*1024 + 4 pad
#define HS_MSTR 260           // 256 + 4 pad
#define HS_FLOATS (2 * 32 * HS_MSTR)
#define SMEM_FLOATS (8 * VS_JSTR + HS_FLOATS)

__global__ __launch_bounds__(NTH, 1) void lstm_persist(
    const float* __restrict__ Vi, const float* __restrict__ Vf,
    const float* __restrict__ Vc, const float* __restrict__ Vo,
    const float* __restrict__ c0,
    float* __restrict__ out_hs,   // [B][S][H]
    float* __restrict__ out_ht,   // [B][H]
    float* __restrict__ out_ct)   // [B][H]
{
    extern __shared__ float sm[];
    float* Vs = sm;                    // [j][g*1024 + k]
    float* Hs = sm + 8 * VS_JSTR;      // [half*32 + m][k'], stride HS_MSTR

    const int tid = threadIdx.x;
    const int j   = tid & 7;
    const int m   = (tid >> 3) & 31;
    const int kh  = tid >> 8;            // warp-uniform (warps 0-7 vs 8-15)
    const int jb  = blockIdx.x * 8;
    const int jg  = jb + j;

    // ---- one-time V load into smem ----
    for (int e = tid; e < 8 * 4 * 1024; e += NTH) {
        int jj = e & 7;
        int k  = (e >> 3) & 1023;
        int g  = e >> 13;
        const float* Vg = (g == 0) ? Vi : (g == 1) ? Vf : (g == 2) ? Vc : Vo;
        Vs[jj * VS_JSTR + g * 1024 + k] = __ldg(&Vg[(size_t)k * HID + jb + jj]);
    }

    float cc = (kh == 0) ? __ldg(&c0[m * HID + jg]) : 0.f;
    float hlast = 0.f;

    for (int s = 0; s < SEQ; ++s) {
        const float* __restrict__ hsrc = g_h[s & 1];

        float xi = 0.f, xf = 0.f, xg = 0.f, xo = 0.f;
        if (kh == 0) {
            const float* xup = &g_xu[(((size_t)s * BATCH + m) * 4) * HID + jg];
            xi = __ldcs(xup);
            xf = __ldcs(xup + HID);
            xg = __ldcs(xup + 2 * HID);
            xo = __ldcs(xup + 3 * HID);
        }

        unsigned long long a_i = 0, a_f = 0, a_c = 0, a_o = 0;

        // prefetch chunk pair ci=0: region r selects k-half
        float4 hreg[8];
        #pragma unroll
        for (int r = 0; r < 8; ++r) {
            int e  = tid + NTH * r;         // 0..4095 float4 slots
            int rg = e >> 11;               // which k-half's chunk
            int sl = e & 2047;
            int b  = sl >> 6;
            int kq = sl & 63;
            hreg[r] = __ldcg((const float4*)&hsrc[b * HID + rg * 512 + kq * 4]);
        }

        #pragma unroll
        for (int ci = 0; ci < 2; ++ci) {
            __syncthreads();                 // prev chunk compute done
            #pragma unroll
            for (int r = 0; r < 8; ++r) {
                int e  = tid + NTH * r;
                int rg = e >> 11;
                int sl = e & 2047;
                int b  = sl >> 6;
                int kq = sl & 63;
                *(float4*)&Hs[(rg * 32 + b) * HS_MSTR + kq * 4] = hreg[r];
            }
            __syncthreads();
            if (ci == 0) {                   // prefetch next chunk pair
                #pragma unroll
                for (int r = 0; r < 8; ++r) {
                    int e  = tid + NTH * r;
                    int rg = e >> 11;
                    int sl = e & 2047;
                    int b  = sl >> 6;
                    int kq = sl & 63;
                    hreg[r] = __ldcg((const float4*)&hsrc[b * HID + rg * 512 + KCH + kq * 4]);
                }
            }

            const float* vsj = &Vs[j * VS_JSTR + kh * 512 + ci * KCH];
            const float* hsm = &Hs[(kh * 32 + m) * HS_MSTR];
            #pragma unroll 8
            for (int kk = 0; kk < KCH; kk += 4) {
                ulonglong2 h2 = *(const ulonglong2*)&hsm[kk];
                ulonglong2 v;
                v = *(const ulonglong2*)&vsj[0 * 1024 + kk];
                a_i = fma2(h2.x, v.x, a_i); a_i = fma2(h2.y, v.y, a_i);
                v = *(const ulonglong2*)&vsj[1 * 1024 + kk];
                a_f = fma2(h2.x, v.x, a_f); a_f = fma2(h2.y, v.y, a_f);
                v = *(const ulonglong2*)&vsj[2 * 1024 + kk];
                a_c = fma2(h2.x, v.x, a_c); a_c = fma2(h2.y, v.y, a_c);
                v = *(const ulonglong2*)&vsj[3 * 1024 + kk];
                a_o = fma2(h2.x, v.x, a_o); a_o = fma2(h2.y, v.y, a_o);
            }
        }

        // ---- cross-half reduction (conflict-free: [gate][256]) ----
        __syncthreads();                     // done reading Hs; reuse as scratch
        if (kh == 1) {
            float2 p;
            p = unpack2(a_i); Hs[0 * 256 + (tid - 256)] = p.x + p.y;
            p = unpack2(a_f); Hs[1 * 256 + (tid - 256)] = p.x + p.y;
            p = unpack2(a_c); Hs[2 * 256 + (tid - 256)] = p.x + p.y;
            p = unpack2(a_o); Hs[3 * 256 + (tid - 256)] = p.x + p.y;
        }
        __syncthreads();

        if (kh == 0) {
            float2 p;
            p = unpack2(a_i); float zi = xi + p.x + p.y + Hs[0 * 256 + tid];
            p = unpack2(a_f); float zf = xf + p.x + p.y + Hs[1 * 256 + tid];
            p = unpack2(a_c); float zg = xg + p.x + p.y + Hs[2 * 256 + tid];
            p = unpack2(a_o); float zo = xo + p.x + p.y + Hs[3 * 256 + tid];

            float ig = sigmoidf_(zi);
            float fg = sigmoidf_(zf);
            float gg = tanhf(zg);
            float og = sigmoidf_(zo);
            cc = fg * cc + ig * gg;
            float h = og * tanhf(cc);
            hlast = h;

            __stcg(&g_h[(s + 1) & 1][m * HID + jg], h);
            __stcs(&out_hs[((size_t)m * SEQ + s) * HID + jg], h);
        }

        if (s < SEQ - 1) {
            __syncthreads();                 // h stores issued
            if (tid == 0) {
                __threadfence();             // publish h before arriving
                atomicAdd(&g_bar, 1u);
                unsigned target = (unsigned)NCTA * (unsigned)(s + 1);
                unsigned v;
                do {
                    asm volatile("ld.acquire.gpu.u32 %0, [%1];"
                                 : "=r"(v) : "l"(&g_bar));
                } while (v < target);
            }
            __syncthreads();                 // release to whole CTA
        }
    }

    if (kh == 0) {
        out_ht[m * HID + jg] = hlast;
        out_ct[m * HID + jg] = cc;
    }
}

// ---------------------------------------------------------------------------
extern "C" void kernel_launch(void* const* d_in, const int* in_sizes, int n_in,
                              void* d_out, int out_size) {
    const float* x   = (const float*)d_in[0];
    const float* h0  = (const float*)d_in[1];
    const float* c0  = (const float*)d_in[2];
    const float* U_i = (const float*)d_in[3];
    const float* V_i = (const float*)d_in[4];
    const float* b_i = (const float*)d_in[5];
    const float* U_f = (const float*)d_in[6];
    const float* V_f = (const float*)d_in[7];
    const float* b_f = (const float*)d_in[8];
    const float* U_c = (const float*)d_in[9];
    const float* V_c = (const float*)d_in[10];
    const float* b_c = (const float*)d_in[11];
    const float* U_o = (const float*)d_in[12];
    const float* V_o = (const float*)d_in[13];
    const float* b_o = (const float*)d_in[14];

    float* out    = (float*)d_out;
    float* out_hs = out;                                   // [B][S][H]
    float* out_ht = out + (size_t)BATCH * SEQ * HID;       // [B][H]
    float* out_ct = out_ht + (size_t)BATCH * HID;          // [B][H]

    static_assert(SMEM_FLOATS * 4 <= 227000, "smem budget");
    cudaFuncSetAttribute(lstm_persist,
                         cudaFuncAttributeMaxDynamicSharedMemorySize,
                         SMEM_FLOATS * 4);

    init_state<<<128, 256>>>(h0);

    dim3 g1(128, 32);
    xu_gemm<<<g1, 256>>>(x, U_i, U_f, U_c, U_o, b_i, b_f, b_c, b_o);

    lstm_persist<<<NCTA, NTH, SMEM_FLOATS * 4>>>(
        V_i, V_f, V_c, V_o, c0, out_hs, out_ht, out_ct);
}

// round 5
// speedup vs baseline: 2.4436x; 1.7622x over previous
#include <cuda_runtime.h>
#include <cuda_bf16.h>

#define BATCH 32
#define SEQ   512
#define DIM   1024
#define HID   1024
#define NCTA  128
#define NTH   256

typedef unsigned long long ull;

// ---------------- scratch (device globals; no cudaMalloc allowed) ----------
__device__ float g_xu[(size_t)SEQ * BATCH * 4 * HID];  // [s][b][gate][j]
__device__ float g_hT[2][HID * BATCH];                 // transposed h: [par][k][m]
__device__ unsigned g_flags[NCTA * 8];                 // 32B-strided arrival flags

// ---------------- packed f32x2 helpers -------------------------------------
__device__ __forceinline__ ull pack2s(float a) {
    ull r; asm("mov.b64 %0, {%1, %1};" : "=l"(r) : "f"(a)); return r;
}
__device__ __forceinline__ ull fma2(ull a, ull b, ull c) {
    ull d; asm("fma.rn.f32x2 %0, %1, %2, %3;" : "=l"(d) : "l"(a), "l"(b), "l"(c)); return d;
}
__device__ __forceinline__ ull add2(ull a, ull b) {
    ull d; asm("add.rn.f32x2 %0, %1, %2;" : "=l"(d) : "l"(a), "l"(b)); return d;
}
__device__ __forceinline__ float2 unpack2(ull v) {
    float2 r; asm("mov.b64 {%0, %1}, %2;" : "=f"(r.x), "=f"(r.y) : "l"(v)); return r;
}
__device__ __forceinline__ ull shfl_bfly64(ull v, int m) {
    unsigned lo = (unsigned)v, hi = (unsigned)(v >> 32);
    lo = __shfl_xor_sync(0xffffffffu, lo, m);
    hi = __shfl_xor_sync(0xffffffffu, hi, m);
    return ((ull)hi << 32) | lo;
}
__device__ __forceinline__ float sigmoidf_(float x) {
    return 1.0f / (1.0f + __expf(-x));
}

// ---------------------------------------------------------------------------
// Phase 1: g_xu[s][b][g][j] = sum_k x[b][s][k] * U_g[k][j] + b_g[j]
// Block (0,0) also seeds g_hT[0] from h0 and zeroes the barrier flags.
// ---------------------------------------------------------------------------
__global__ __launch_bounds__(256, 2) void xu_gemm(
    const float* __restrict__ x,  const float* __restrict__ h0,
    const float* __restrict__ Ui, const float* __restrict__ Uf,
    const float* __restrict__ Uc, const float* __restrict__ Uo,
    const float* __restrict__ bi, const float* __restrict__ bf,
    const float* __restrict__ bc, const float* __restrict__ bo)
{
    __shared__ float As[32 * 132];
    __shared__ float Bs[32 * 132];

    const int tid = threadIdx.x;

    if (blockIdx.x == 0 && blockIdx.y == 0) {
        for (int e = tid; e < BATCH * HID; e += 256) {
            int m = e & 31;
            int k = e >> 5;
            g_hT[0][k * BATCH + m] = h0[m * HID + k];
        }
        for (int e = tid; e < NCTA * 8; e += 256) g_flags[e] = 0;
    }

    const int m0   = blockIdx.x * 128;
    const int by   = blockIdx.y;
    const int gate = by >> 3;
    const int j0   = (by & 7) * 128;

    const float* U    = (gate == 0) ? Ui : (gate == 1) ? Uf : (gate == 2) ? Uc : Uo;
    const float* bias = (gate == 0) ? bi : (gate == 1) ? bf : (gate == 2) ? bc : bo;

    const int tn = tid & 15;
    const int tm = tid >> 4;

    ull acc2[8][4];
    #pragma unroll
    for (int i = 0; i < 8; i++)
        #pragma unroll
        for (int j = 0; j < 4; j++) acc2[i][j] = 0ULL;

    for (int k0 = 0; k0 < DIM; k0 += 32) {
        #pragma unroll
        for (int r = 0; r < 4; ++r) {
            int f4  = tid + 256 * r;
            int row = f4 >> 3;
            int c4  = f4 & 7;
            float4 v = *(const float4*)&x[(size_t)(m0 + row) * DIM + k0 + c4 * 4];
            As[(c4 * 4 + 0) * 132 + row] = v.x;
            As[(c4 * 4 + 1) * 132 + row] = v.y;
            As[(c4 * 4 + 2) * 132 + row] = v.z;
            As[(c4 * 4 + 3) * 132 + row] = v.w;
        }
        #pragma unroll
        for (int r = 0; r < 4; ++r) {
            int f4  = tid + 256 * r;
            int row = f4 >> 5;
            int c4  = f4 & 31;
            *(float4*)&Bs[row * 132 + c4 * 4] =
                *(const float4*)&U[(size_t)(k0 + row) * HID + j0 + c4 * 4];
        }
        __syncthreads();

        #pragma unroll 8
        for (int kk = 0; kk < 32; ++kk) {
            float4 a0 = *(const float4*)&As[kk * 132 + tm * 8];
            float4 a1 = *(const float4*)&As[kk * 132 + tm * 8 + 4];
            ulonglong2 b0 = *(const ulonglong2*)&Bs[kk * 132 + tn * 8];
            ulonglong2 b1 = *(const ulonglong2*)&Bs[kk * 132 + tn * 8 + 4];
            ull bv[4] = {b0.x, b0.y, b1.x, b1.y};
            float av[8] = {a0.x, a0.y, a0.z, a0.w, a1.x, a1.y, a1.z, a1.w};
            #pragma unroll
            for (int i = 0; i < 8; i++) {
                ull aa = pack2s(av[i]);
                #pragma unroll
                for (int jp = 0; jp < 4; jp++)
                    acc2[i][jp] = fma2(aa, bv[jp], acc2[i][jp]);
            }
        }
        __syncthreads();
    }

    float bv[8];
    #pragma unroll
    for (int j = 0; j < 8; j++) bv[j] = bias[j0 + tn * 8 + j];

    #pragma unroll
    for (int i = 0; i < 8; i++) {
        int m  = m0 + tm * 8 + i;
        int b_ = m >> 9;
        int s_ = m & 511;
        float* dst = &g_xu[(((size_t)s_ * BATCH + b_) * 4 + gate) * HID + j0 + tn * 8];
        float2 p0 = unpack2(acc2[i][0]);
        float2 p1 = unpack2(acc2[i][1]);
        float2 p2 = unpack2(acc2[i][2]);
        float2 p3 = unpack2(acc2[i][3]);
        float4 r0 = make_float4(p0.x + bv[0], p0.y + bv[1], p1.x + bv[2], p1.y + bv[3]);
        float4 r1 = make_float4(p2.x + bv[4], p2.y + bv[5], p3.x + bv[6], p3.y + bv[7]);
        *(float4*)&dst[0] = r0;
        *(float4*)&dst[4] = r1;
    }
}

// ---------------------------------------------------------------------------
// Phase 2: PERSISTENT recurrence, register-tiled (8m x 8col per thread,
// k-split 16). Vs [1024][36] resident in smem; Hs [256][36] staged per chunk
// from transposed g_hT; Hs reused as reduction scratch [8][1032].
// ---------------------------------------------------------------------------
#define VS_STR 36
#define HS_STR 36
#define SC_STR 1032
#define SMEM_FLOATS (1024 * VS_STR + 256 * HS_STR)

__global__ __launch_bounds__(NTH, 1) void lstm_persist(
    const float* __restrict__ Vi, const float* __restrict__ Vf,
    const float* __restrict__ Vc, const float* __restrict__ Vo,
    const float* __restrict__ c0,
    float* __restrict__ out_hs,
    float* __restrict__ out_ht,
    float* __restrict__ out_ct)
{
    extern __shared__ float sm[];
    float* Vs = sm;                      // [1024][VS_STR]
    float* Hs = sm + 1024 * VS_STR;      // [256][HS_STR] / scratch [8][SC_STR]

    const int tid  = threadIdx.x;
    const int ks   = tid >> 4;
    const int pos  = tid & 15;
    const int mi   = pos >> 2;
    const int ci   = pos & 3;
    const int w    = tid >> 5;
    const int lane = tid & 31;
    const int jb   = blockIdx.x * 8;

    const int fm  = tid >> 3;
    const int fj  = tid & 7;
    const int fjg = jb + fj;

    for (int e = tid; e < 1024 * 32; e += NTH) {
        int k   = e >> 5;
        int col = e & 31;
        int j   = col >> 2;
        int g   = col & 3;
        const float* Vg = (g == 0) ? Vi : (g == 1) ? Vf : (g == 2) ? Vc : Vo;
        Vs[k * VS_STR + col] = __ldg(&Vg[(size_t)k * HID + jb + j]);
    }
    float cc = __ldg(&c0[fm * HID + fjg]);
    __syncthreads();

    for (int s = 0; s < SEQ; ++s) {
        const float* __restrict__ hsrc = g_hT[s & 1];

        const float* xup = &g_xu[(((size_t)s * BATCH + fm) * 4) * HID + fjg];
        float xi = __ldcs(xup);
        float xf = __ldcs(xup + HID);
        float xg = __ldcs(xup + 2 * HID);
        float xo = __ldcs(xup + 3 * HID);

        ull acc[8][4];
        #pragma unroll
        for (int i = 0; i < 8; i++)
            #pragma unroll
            for (int jp = 0; jp < 4; jp++) acc[i][jp] = 0ULL;

        float4 hreg[8];
        #pragma unroll
        for (int r = 0; r < 8; ++r) {
            int idx = r * 256 + tid;
            int kr  = idx >> 3;
            int mq  = idx & 7;
            hreg[r] = __ldcg((const float4*)&hsrc[kr * 32 + mq * 4]);
        }

        #pragma unroll
        for (int ch = 0; ch < 4; ++ch) {
            __syncthreads();
            #pragma unroll
            for (int r = 0; r < 8; ++r) {
                int idx = r * 256 + tid;
                int kr  = idx >> 3;
                int mq  = idx & 7;
                *(float4*)&Hs[kr * HS_STR + mq * 4] = hreg[r];
            }
            __syncthreads();
            if (ch < 3) {
                #pragma unroll
                for (int r = 0; r < 8; ++r) {
                    int idx = r * 256 + tid;
                    int kr  = idx >> 3;
                    int mq  = idx & 7;
                    hreg[r] = __ldcg((const float4*)&hsrc[((ch + 1) * 256 + kr) * 32 + mq * 4]);
                }
            }

            const float* hb = &Hs[(ks * 16) * HS_STR + mi * 8];
            const float* vb = &Vs[(ch * 256 + ks * 16) * VS_STR + ci * 8];
            #pragma unroll
            for (int kk = 0; kk < 16; ++kk) {
                float4 h0 = *(const float4*)&hb[kk * HS_STR];
                float4 h1 = *(const float4*)&hb[kk * HS_STR + 4];
                ulonglong2 v0 = *(const ulonglong2*)&vb[kk * VS_STR];
                ulonglong2 v1 = *(const ulonglong2*)&vb[kk * VS_STR + 4];
                ull  vv[4] = {v0.x, v0.y, v1.x, v1.y};
                float hv[8] = {h0.x, h0.y, h0.z, h0.w, h1.x, h1.y, h1.z, h1.w};
                #pragma unroll
                for (int im = 0; im < 8; im++) {
                    ull hh = pack2s(hv[im]);
                    #pragma unroll
                    for (int jp = 0; jp < 4; jp++)
                        acc[im][jp] = fma2(hh, vv[jp], acc[im][jp]);
                }
            }
        }

        #pragma unroll
        for (int im = 0; im < 8; im++)
            #pragma unroll
            for (int jp = 0; jp < 4; jp++)
                acc[im][jp] = add2(acc[im][jp], shfl_bfly64(acc[im][jp], 16));

        __syncthreads();
        if (lane < 16) {
            #pragma unroll
            for (int im = 0; im < 8; im++) {
                int ob = (mi * 8 + im) * 32 + ci * 8;
                ulonglong2 q0; q0.x = acc[im][0]; q0.y = acc[im][1];
                ulonglong2 q1; q1.x = acc[im][2]; q1.y = acc[im][3];
                *(ulonglong2*)&Hs[w * SC_STR + ob]     = q0;
                *(ulonglong2*)&Hs[w * SC_STR + ob + 4] = q1;
            }
        }
        __syncthreads();

        float zi = xi, zf = xf, zg = xg, zo = xo;
        #pragma unroll
        for (int w8 = 0; w8 < 8; ++w8) {
            float4 p = *(const float4*)&Hs[w8 * SC_STR + 4 * tid];
            zi += p.x; zf += p.y; zg += p.z; zo += p.w;
        }

        float ig = sigmoidf_(zi);
        float fg = sigmoidf_(zf);
        float gg = tanhf(zg);
        float og = sigmoidf_(zo);
        cc = fg * cc + ig * gg;
        float h = og * tanhf(cc);

        g_hT[(s + 1) & 1][fjg * 32 + fm] = h;
        __stcs(&out_hs[((size_t)fm * SEQ + s) * HID + fjg], h);

        if (s == SEQ - 1) {
            out_ht[fm * HID + fjg] = h;
            out_ct[fm * HID + fjg] = cc;
        } else {
            __syncthreads();
            if (tid == 0) {
                asm volatile("st.release.gpu.global.u32 [%0], %1;"
                             :: "l"(&g_flags[blockIdx.x * 8]), "r"((unsigned)(s + 1))
                             : "memory");
            }
            if (w == 0) {
                unsigned target = (unsigned)(s + 1);
                bool ok;
                do {
                    ok = true;
                    #pragma unroll
                    for (int q = 0; q < 4; ++q) {
                        unsigned v;
                        asm volatile("ld.acquire.gpu.global.u32 %0, [%1];"
                                     : "=r"(v)
                                     : "l"(&g_flags[(lane + 32 * q) * 8]));
                        ok = ok && (v >= target);
                    }
                } while (!__all_sync(0xffffffffu, ok));
            }
            __syncthreads();
        }
    }
}

// ---------------------------------------------------------------------------
extern "C" void kernel_launch(void* const* d_in, const int* in_sizes, int n_in,
                              void* d_out, int out_size) {
    const float* x   = (const float*)d_in[0];
    const float* h0  = (const float*)d_in[1];
    const float* c0  = (const float*)d_in[2];
    const float* U_i = (const float*)d_in[3];
    const float* V_i = (const float*)d_in[4];
    const float* b_i = (const float*)d_in[5];
    const float* U_f = (const float*)d_in[6];
    const float* V_f = (const float*)d_in[7];
    const float* b_f = (const float*)d_in[8];
    const float* U_c = (const float*)d_in[9];
    const float* V_c = (const float*)d_in[10];
    const float* b_c = (const float*)d_in[11];
    const float* U_o = (const float*)d_in[12];
    const float* V_o = (const float*)d_in[13];
    const float* b_o = (const float*)d_in[14];

    float* out    = (float*)d_out;
    float* out_hs = out;
    float* out_ht = out + (size_t)BATCH * SEQ * HID;
    float* out_ct = out_ht + (size_t)BATCH * HID;

    static_assert(SMEM_FLOATS * 4 <= 227000, "smem budget");
    cudaFuncSetAttribute(lstm_persist,
                         cudaFuncAttributeMaxDynamicSharedMemorySize,
                         SMEM_FLOATS * 4);

    dim3 g1(128, 32);
    xu_gemm<<<g1, 256>>>(x, h0, U_i, U_f, U_c, U_o, b_i, b_f, b_c, b_o);

    lstm_persist<<<NCTA, NTH, SMEM_FLOATS * 4>>>(
        V_i, V_f, V_c, V_o, c0, out_hs, out_ht, out_ct);
}

// round 6
// speedup vs baseline: 3.0819x; 1.2612x over previous
#include <cuda_runtime.h>
#include <cuda_bf16.h>

#define BATCH 32
#define SEQ   512
#define DIM   1024
#define HID   1024
#define NCTA  128
#define NTH   256

typedef unsigned long long ull;

// ---------------- scratch (device globals; no cudaMalloc allowed) ----------
__device__ float g_xu[(size_t)SEQ * BATCH * 4 * HID];   // [s][b][gate][j]
__device__ float g_hT[2][HID * BATCH];                  // transposed h: [par][k][m]
__device__ unsigned g_flags[NCTA * 8];                  // 32B-strided arrival flags
__device__ __nv_bfloat16 g_xh[(size_t)16384 * 1024];    // x hi  [m][k]
__device__ __nv_bfloat16 g_xl[(size_t)16384 * 1024];    // x lo
__device__ __nv_bfloat16 g_uh[(size_t)4 * 1024 * 1024]; // U hi  [g][k][n]
__device__ __nv_bfloat16 g_ul[(size_t)4 * 1024 * 1024]; // U lo

// ---------------- packed f32x2 helpers -------------------------------------
__device__ __forceinline__ ull pack2s(float a) {
    ull r; asm("mov.b64 %0, {%1, %1};" : "=l"(r) : "f"(a)); return r;
}
__device__ __forceinline__ ull fma2(ull a, ull b, ull c) {
    ull d; asm("fma.rn.f32x2 %0, %1, %2, %3;" : "=l"(d) : "l"(a), "l"(b), "l"(c)); return d;
}
__device__ __forceinline__ ull add2(ull a, ull b) {
    ull d; asm("add.rn.f32x2 %0, %1, %2;" : "=l"(d) : "l"(a), "l"(b)); return d;
}
__device__ __forceinline__ float2 unpack2(ull v) {
    float2 r; asm("mov.b64 {%0, %1}, %2;" : "=f"(r.x), "=f"(r.y) : "l"(v)); return r;
}
__device__ __forceinline__ ull shfl_bfly64(ull v, int m) {
    unsigned lo = (unsigned)v, hi = (unsigned)(v >> 32);
    lo = __shfl_xor_sync(0xffffffffu, lo, m);
    hi = __shfl_xor_sync(0xffffffffu, hi, m);
    return ((ull)hi << 32) | lo;
}
__device__ __forceinline__ float sigmoidf_(float x) {
    return 1.0f / (1.0f + __expf(-x));
}

// ---------------- tensor-core helpers ---------------------------------------
__device__ __forceinline__ unsigned smem_u32(const void* p) {
    return (unsigned)__cvta_generic_to_shared(p);
}
__device__ __forceinline__ void ldm_x4(unsigned* r, unsigned addr) {
    asm volatile("ldmatrix.sync.aligned.m8n8.x4.shared.b16 {%0,%1,%2,%3}, [%4];"
                 : "=r"(r[0]), "=r"(r[1]), "=r"(r[2]), "=r"(r[3]) : "r"(addr));
}
__device__ __forceinline__ void ldm_x4t(unsigned* r, unsigned addr) {
    asm volatile("ldmatrix.sync.aligned.m8n8.x4.trans.shared.b16 {%0,%1,%2,%3}, [%4];"
                 : "=r"(r[0]), "=r"(r[1]), "=r"(r[2]), "=r"(r[3]) : "r"(addr));
}
__device__ __forceinline__ void mma_bf16(float* d, const unsigned* a, const unsigned* b) {
    asm volatile(
        "mma.sync.aligned.m16n8k16.row.col.f32.bf16.bf16.f32 "
        "{%0,%1,%2,%3}, {%4,%5,%6,%7}, {%8,%9}, {%0,%1,%2,%3};"
        : "+f"(d[0]), "+f"(d[1]), "+f"(d[2]), "+f"(d[3])
        : "r"(a[0]), "r"(a[1]), "r"(a[2]), "r"(a[3]), "r"(b[0]), "r"(b[1]));
}

// ---------------------------------------------------------------------------
// init: g_hT[0] = h0 transposed; barrier flags = 0
// ---------------------------------------------------------------------------
__global__ void init_state(const float* __restrict__ h0) {
    int idx = blockIdx.x * 256 + threadIdx.x;   // 0 .. 32767
    int m = idx & 31;
    int k = idx >> 5;
    g_hT[0][k * BATCH + m] = h0[m * HID + k];
    if (idx < NCTA * 8) g_flags[idx] = 0;
}

// ---------------------------------------------------------------------------
// cvt_split: fp32 -> (bf16 hi, bf16 lo) for x and the 4 gate U matrices.
// ---------------------------------------------------------------------------
#define XN4 ((size_t)16384 * 1024 / 4)
#define UG4 ((size_t)1024 * 1024 / 4)
__global__ __launch_bounds__(256) void cvt_split(
    const float* __restrict__ x,
    const float* __restrict__ Ui, const float* __restrict__ Uf,
    const float* __restrict__ Uc, const float* __restrict__ Uo)
{
    size_t i4 = (size_t)blockIdx.x * 256 + threadIdx.x;
    const float4* src;
    __nv_bfloat162* dh;
    __nv_bfloat162* dl;
    size_t off;
    if (i4 < XN4) {
        src = (const float4*)x;   off = i4;
        dh = (__nv_bfloat162*)g_xh;
        dl = (__nv_bfloat162*)g_xl;
    } else {
        size_t j = i4 - XN4;
        int g = (int)(j >> 18);               // UG4 = 2^18
        size_t o = j & (UG4 - 1);
        const float* Ug = (g == 0) ? Ui : (g == 1) ? Uf : (g == 2) ? Uc : Uo;
        src = (const float4*)Ug;  off = o;
        dh = (__nv_bfloat162*)(g_uh + (size_t)g * 1024 * 1024);
        dl = (__nv_bfloat162*)(g_ul + (size_t)g * 1024 * 1024);
    }
    float4 v = src[off];
    __nv_bfloat16 h0 = __float2bfloat16_rn(v.x);
    __nv_bfloat16 h1 = __float2bfloat16_rn(v.y);
    __nv_bfloat16 h2 = __float2bfloat16_rn(v.z);
    __nv_bfloat16 h3 = __float2bfloat16_rn(v.w);
    __nv_bfloat16 l0 = __float2bfloat16_rn(v.x - __bfloat162float(h0));
    __nv_bfloat16 l1 = __float2bfloat16_rn(v.y - __bfloat162float(h1));
    __nv_bfloat16 l2 = __float2bfloat16_rn(v.z - __bfloat162float(h2));
    __nv_bfloat16 l3 = __float2bfloat16_rn(v.w - __bfloat162float(h3));
    dh[off * 2]     = __halves2bfloat162(h0, h1);
    dh[off * 2 + 1] = __halves2bfloat162(h2, h3);
    dl[off * 2]     = __halves2bfloat162(l0, l1);
    dl[off * 2 + 1] = __halves2bfloat162(l2, l3);
}

// ---------------------------------------------------------------------------
// Phase 1 on tensor cores: g_xu = x @ U_g + b_g via split-bf16 mma.sync.
// CTA 128(M) x 128(N), 8 warps each 32m x 64n, K-chunks of 32.
// acc += Ah*Bh + Al*Bh + Ah*Bl  (lo*lo dropped).
// ---------------------------------------------------------------------------
#define AS_STR 40     // bf16 row stride for A smem (ldmatrix conflict-free)
#define BS_STR 136    // bf16 row stride for B smem

__global__ __launch_bounds__(256, 2) void xu_mma(
    const float* __restrict__ bi, const float* __restrict__ bf,
    const float* __restrict__ bc, const float* __restrict__ bo)
{
    __shared__ __nv_bfloat16 Ash[128 * AS_STR];
    __shared__ __nv_bfloat16 Asl[128 * AS_STR];
    __shared__ __nv_bfloat16 Bsh[32 * BS_STR];
    __shared__ __nv_bfloat16 Bsl[32 * BS_STR];

    const int tid  = threadIdx.x;
    const int wid  = tid >> 5;
    const int lane = tid & 31;
    const int wm   = wid & 3;          // m offset = wm*32
    const int wn   = wid >> 2;         // n offset = wn*64
    const int m0   = blockIdx.x * 128;
    const int nb   = blockIdx.y;       // 0..31
    const int gate = nb >> 3;
    const int j0   = (nb & 7) * 128;

    const float* bias = (gate == 0) ? bi : (gate == 1) ? bf : (gate == 2) ? bc : bo;
    const __nv_bfloat16* __restrict__ Agh = g_xh;
    const __nv_bfloat16* __restrict__ Agl = g_xl;
    const __nv_bfloat16* __restrict__ Bgh = g_uh + (size_t)gate * 1024 * 1024;
    const __nv_bfloat16* __restrict__ Bgl = g_ul + (size_t)gate * 1024 * 1024;

    float acc[2][8][4];
    #pragma unroll
    for (int ti = 0; ti < 2; ti++)
        #pragma unroll
        for (int tj = 0; tj < 8; tj++)
            #pragma unroll
            for (int q = 0; q < 4; q++) acc[ti][tj][q] = 0.f;

    // per-thread staging indices
    const int ar = tid >> 2;           // A row (2 rows per thread via +64)
    const int ac = tid & 3;            // A uint4 col
    const int br = tid >> 4;           // B row (2 rows via +16)
    const int bc2 = tid & 15;          // B uint4 col

    // ldmatrix lane addresses (element offsets)
    const int a_r = (lane & 15);               // row within m16 tile
    const int a_c = (lane >> 4) << 3;          // k sub-offset 0/8
    const int b_k = (lane & 15);               // k row within k16
    const int b_n = (lane >> 4) << 3;          // n sub-offset 0/8

    for (int k0 = 0; k0 < DIM; k0 += 32) {
        // global loads (16B each)
        uint4 avh[2], avl[2], bvh[2], bvl[2];
        #pragma unroll
        for (int u = 0; u < 2; ++u) {
            int row = ar + u * 64;
            const uint4* ph = (const uint4*)&Agh[(size_t)(m0 + row) * DIM + k0 + ac * 8];
            const uint4* pl = (const uint4*)&Agl[(size_t)(m0 + row) * DIM + k0 + ac * 8];
            avh[u] = __ldg(ph);
            avl[u] = __ldg(pl);
            int krow = br + u * 16;
            const uint4* qh = (const uint4*)&Bgh[(size_t)(k0 + krow) * HID + j0 + bc2 * 8];
            const uint4* ql = (const uint4*)&Bgl[(size_t)(k0 + krow) * HID + j0 + bc2 * 8];
            bvh[u] = __ldg(qh);
            bvl[u] = __ldg(ql);
        }
        __syncthreads();   // previous chunk compute done
        #pragma unroll
        for (int u = 0; u < 2; ++u) {
            int row = ar + u * 64;
            *(uint4*)&Ash[row * AS_STR + ac * 8] = avh[u];
            *(uint4*)&Asl[row * AS_STR + ac * 8] = avl[u];
            int krow = br + u * 16;
            *(uint4*)&Bsh[krow * BS_STR + bc2 * 8] = bvh[u];
            *(uint4*)&Bsl[krow * BS_STR + bc2 * 8] = bvl[u];
        }
        __syncthreads();

        #pragma unroll
        for (int kk = 0; kk < 32; kk += 16) {
            unsigned Ah[2][4], Al[2][4], Bf[4][4];
            #pragma unroll
            for (int ti = 0; ti < 2; ++ti) {
                int row = wm * 32 + ti * 16 + a_r;
                ldm_x4(Ah[ti], smem_u32(&Ash[row * AS_STR + kk + a_c]));
                ldm_x4(Al[ti], smem_u32(&Asl[row * AS_STR + kk + a_c]));
            }
            #pragma unroll
            for (int p = 0; p < 4; ++p) {
                int n = wn * 64 + p * 16 + b_n;
                ldm_x4t(Bf[p], smem_u32(&Bsh[(kk + b_k) * BS_STR + n]));
            }
            #pragma unroll
            for (int ti = 0; ti < 2; ++ti)
                #pragma unroll
                for (int p = 0; p < 4; ++p) {
                    mma_bf16(acc[ti][2 * p],     Ah[ti], &Bf[p][0]);
                    mma_bf16(acc[ti][2 * p + 1], Ah[ti], &Bf[p][2]);
                    mma_bf16(acc[ti][2 * p],     Al[ti], &Bf[p][0]);
                    mma_bf16(acc[ti][2 * p + 1], Al[ti], &Bf[p][2]);
                }
            #pragma unroll
            for (int p = 0; p < 4; ++p) {
                int n = wn * 64 + p * 16 + b_n;
                ldm_x4t(Bf[p], smem_u32(&Bsl[(kk + b_k) * BS_STR + n]));
            }
            #pragma unroll
            for (int ti = 0; ti < 2; ++ti)
                #pragma unroll
                for (int p = 0; p < 4; ++p) {
                    mma_bf16(acc[ti][2 * p],     Ah[ti], &Bf[p][0]);
                    mma_bf16(acc[ti][2 * p + 1], Ah[ti], &Bf[p][2]);
                }
        }
    }

    // epilogue: add bias (fp32), write to g_xu [s][b][gate][j]
    #pragma unroll
    for (int ti = 0; ti < 2; ++ti) {
        #pragma unroll
        for (int tj = 0; tj < 8; ++tj) {
            int col = j0 + wn * 64 + tj * 8 + (lane & 3) * 2;
            float c0 = __ldg(&bias[col]);
            float c1 = __ldg(&bias[col + 1]);
            int row0 = m0 + wm * 32 + ti * 16 + (lane >> 2);
            int row1 = row0 + 8;
            {
                int b_ = row0 >> 9, s_ = row0 & 511;
                float2* dst = (float2*)&g_xu[(((size_t)s_ * BATCH + b_) * 4 + gate) * HID + col];
                *dst = make_float2(acc[ti][tj][0] + c0, acc[ti][tj][1] + c1);
            }
            {
                int b_ = row1 >> 9, s_ = row1 & 511;
                float2* dst = (float2*)&g_xu[(((size_t)s_ * BATCH + b_) * 4 + gate) * HID + col];
                *dst = make_float2(acc[ti][tj][2] + c0, acc[ti][tj][3] + c1);
            }
        }
    }
}

// ---------------------------------------------------------------------------
// Phase 2: PERSISTENT recurrence, register-tiled (unchanged from R5 winner).
// ---------------------------------------------------------------------------
#define VS_STR 36
#define HS_STR 36
#define SC_STR 1032
#define SMEM_FLOATS (1024 * VS_STR + 256 * HS_STR)

__global__ __launch_bounds__(NTH, 1) void lstm_persist(
    const float* __restrict__ Vi, const float* __restrict__ Vf,
    const float* __restrict__ Vc, const float* __restrict__ Vo,
    const float* __restrict__ c0,
    float* __restrict__ out_hs,
    float* __restrict__ out_ht,
    float* __restrict__ out_ct)
{
    extern __shared__ float sm[];
    float* Vs = sm;                      // [1024][VS_STR]
    float* Hs = sm + 1024 * VS_STR;      // [256][HS_STR] / scratch [8][SC_STR]

    const int tid  = threadIdx.x;
    const int ks   = tid >> 4;
    const int pos  = tid & 15;
    const int mi   = pos >> 2;
    const int ci   = pos & 3;
    const int w    = tid >> 5;
    const int lane = tid & 31;
    const int jb   = blockIdx.x * 8;

    const int fm  = tid >> 3;
    const int fj  = tid & 7;
    const int fjg = jb + fj;

    for (int e = tid; e < 1024 * 32; e += NTH) {
        int k   = e >> 5;
        int col = e & 31;
        int j   = col >> 2;
        int g   = col & 3;
        const float* Vg = (g == 0) ? Vi : (g == 1) ? Vf : (g == 2) ? Vc : Vo;
        Vs[k * VS_STR + col] = __ldg(&Vg[(size_t)k * HID + jb + j]);
    }
    float cc = __ldg(&c0[fm * HID + fjg]);
    __syncthreads();

    for (int s = 0; s < SEQ; ++s) {
        const float* __restrict__ hsrc = g_hT[s & 1];

        const float* xup = &g_xu[(((size_t)s * BATCH + fm) * 4) * HID + fjg];
        float xi = __ldcs(xup);
        float xf = __ldcs(xup + HID);
        float xg = __ldcs(xup + 2 * HID);
        float xo = __ldcs(xup + 3 * HID);

        ull acc[8][4];
        #pragma unroll
        for (int i = 0; i < 8; i++)
            #pragma unroll
            for (int jp = 0; jp < 4; jp++) acc[i][jp] = 0ULL;

        float4 hreg[8];
        #pragma unroll
        for (int r = 0; r < 8; ++r) {
            int idx = r * 256 + tid;
            int kr  = idx >> 3;
            int mq  = idx & 7;
            hreg[r] = __ldcg((const float4*)&hsrc[kr * 32 + mq * 4]);
        }

        #pragma unroll
        for (int ch = 0; ch < 4; ++ch) {
            __syncthreads();
            #pragma unroll
            for (int r = 0; r < 8; ++r) {
                int idx = r * 256 + tid;
                int kr  = idx >> 3;
                int mq  = idx & 7;
                *(float4*)&Hs[kr * HS_STR + mq * 4] = hreg[r];
            }
            __syncthreads();
            if (ch < 3) {
                #pragma unroll
                for (int r = 0; r < 8; ++r) {
                    int idx = r * 256 + tid;
                    int kr  = idx >> 3;
                    int mq  = idx & 7;
                    hreg[r] = __ldcg((const float4*)&hsrc[((ch + 1) * 256 + kr) * 32 + mq * 4]);
                }
            }

            const float* hb = &Hs[(ks * 16) * HS_STR + mi * 8];
            const float* vb = &Vs[(ch * 256 + ks * 16) * VS_STR + ci * 8];
            #pragma unroll
            for (int kk = 0; kk < 16; ++kk) {
                float4 h0 = *(const float4*)&hb[kk * HS_STR];
                float4 h1 = *(const float4*)&hb[kk * HS_STR + 4];
                ulonglong2 v0 = *(const ulonglong2*)&vb[kk * VS_STR];
                ulonglong2 v1 = *(const ulonglong2*)&vb[kk * VS_STR + 4];
                ull  vv[4] = {v0.x, v0.y, v1.x, v1.y};
                float hv[8] = {h0.x, h0.y, h0.z, h0.w, h1.x, h1.y, h1.z, h1.w};
                #pragma unroll
                for (int im = 0; im < 8; im++) {
                    ull hh = pack2s(hv[im]);
                    #pragma unroll
                    for (int jp = 0; jp < 4; jp++)
                        acc[im][jp] = fma2(hh, vv[jp], acc[im][jp]);
                }
            }
        }

        #pragma unroll
        for (int im = 0; im < 8; im++)
            #pragma unroll
            for (int jp = 0; jp < 4; jp++)
                acc[im][jp] = add2(acc[im][jp], shfl_bfly64(acc[im][jp], 16));

        __syncthreads();
        if (lane < 16) {
            #pragma unroll
            for (int im = 0; im < 8; im++) {
                int ob = (mi * 8 + im) * 32 + ci * 8;
                ulonglong2 q0; q0.x = acc[im][0]; q0.y = acc[im][1];
                ulonglong2 q1; q1.x = acc[im][2]; q1.y = acc[im][3];
                *(ulonglong2*)&Hs[w * SC_STR + ob]     = q0;
                *(ulonglong2*)&Hs[w * SC_STR + ob + 4] = q1;
            }
        }
        __syncthreads();

        float zi = xi, zf = xf, zg = xg, zo = xo;
        #pragma unroll
        for (int w8 = 0; w8 < 8; ++w8) {
            float4 p = *(const float4*)&Hs[w8 * SC_STR + 4 * tid];
            zi += p.x; zf += p.y; zg += p.z; zo += p.w;
        }

        float ig = sigmoidf_(zi);
        float fg = sigmoidf_(zf);
        float gg = tanhf(zg);
        float og = sigmoidf_(zo);
        cc = fg * cc + ig * gg;
        float h = og * tanhf(cc);

        g_hT[(s + 1) & 1][fjg * 32 + fm] = h;
        __stcs(&out_hs[((size_t)fm * SEQ + s) * HID + fjg], h);

        if (s == SEQ - 1) {
            out_ht[fm * HID + fjg] = h;
            out_ct[fm * HID + fjg] = cc;
        } else {
            __syncthreads();
            if (tid == 0) {
                asm volatile("st.release.gpu.global.u32 [%0], %1;"
                             :: "l"(&g_flags[blockIdx.x * 8]), "r"((unsigned)(s + 1))
                             : "memory");
            }
            if (w == 0) {
                unsigned target = (unsigned)(s + 1);
                bool ok;
                do {
                    ok = true;
                    #pragma unroll
                    for (int q = 0; q < 4; ++q) {
                        unsigned v;
                        asm volatile("ld.acquire.gpu.global.u32 %0, [%1];"
                                     : "=r"(v)
                                     : "l"(&g_flags[(lane + 32 * q) * 8]));
                        ok = ok && (v >= target);
                    }
                } while (!__all_sync(0xffffffffu, ok));
            }
            __syncthreads();
        }
    }
}

// ---------------------------------------------------------------------------
extern "C" void kernel_launch(void* const* d_in, const int* in_sizes, int n_in,
                              void* d_out, int out_size) {
    const float* x   = (const float*)d_in[0];
    const float* h0  = (const float*)d_in[1];
    const float* c0  = (const float*)d_in[2];
    const float* U_i = (const float*)d_in[3];
    const float* V_i = (const float*)d_in[4];
    const float* b_i = (const float*)d_in[5];
    const float* U_f = (const float*)d_in[6];
    const float* V_f = (const float*)d_in[7];
    const float* b_f = (const float*)d_in[8];
    const float* U_c = (const float*)d_in[9];
    const float* V_c = (const float*)d_in[10];
    const float* b_c = (const float*)d_in[11];
    const float* U_o = (const float*)d_in[12];
    const float* V_o = (const float*)d_in[13];
    const float* b_o = (const float*)d_in[14];

    float* out    = (float*)d_out;
    float* out_hs = out;
    float* out_ht = out + (size_t)BATCH * SEQ * HID;
    float* out_ct = out_ht + (size_t)BATCH * HID;

    static_assert(SMEM_FLOATS * 4 <= 227000, "smem budget");
    cudaFuncSetAttribute(lstm_persist,
                         cudaFuncAttributeMaxDynamicSharedMemorySize,
                         SMEM_FLOATS * 4);

    init_state<<<128, 256>>>(h0);

    size_t total4 = XN4 + 4 * UG4;
    cvt_split<<<(unsigned)(total4 / 256), 256>>>(x, U_i, U_f, U_c, U_o);

    dim3 g1(128, 32);
    xu_mma<<<g1, 256>>>(b_i, b_f, b_c, b_o);

    lstm_persist<<<NCTA, NTH, SMEM_FLOATS * 4>>>(
        V_i, V_f, V_c, V_o, c0, out_hs, out_ht, out_ct);
}

// round 7
// speedup vs baseline: 3.7244x; 1.2085x over previous
#include <cuda_runtime.h>
#include <cuda_bf16.h>

#define BATCH 32
#define SEQ   512
#define DIM   1024
#define HID   1024
#define NCTA  128
#define NTH   256

typedef unsigned long long ull;

// ---------------- scratch (device globals; no cudaMalloc allowed) ----------
__device__ float g_xu[(size_t)SEQ * BATCH * 4 * HID];   // [s][b][gate][j]
__device__ unsigned g_flags[NCTA * 8];                  // 32B-strided arrival flags
__device__ __nv_bfloat16 g_xh[(size_t)16384 * 1024];    // x hi  [m][k]
__device__ __nv_bfloat16 g_xl[(size_t)16384 * 1024];    // x lo
__device__ __nv_bfloat16 g_uh[(size_t)4 * 1024 * 1024]; // U hi  [g][k][n]
__device__ __nv_bfloat16 g_ul[(size_t)4 * 1024 * 1024]; // U lo
__device__ __nv_bfloat16 g_hbh[2][BATCH * HID];         // h hi [par][m][k]
__device__ __nv_bfloat16 g_hbl[2][BATCH * HID];         // h lo [par][m][k]

__device__ __forceinline__ float sigmoidf_(float x) {
    return 1.0f / (1.0f + __expf(-x));
}

// ---------------- tensor-core helpers ---------------------------------------
__device__ __forceinline__ unsigned smem_u32(const void* p) {
    return (unsigned)__cvta_generic_to_shared(p);
}
__device__ __forceinline__ void ldm_x4(unsigned* r, unsigned addr) {
    asm volatile("ldmatrix.sync.aligned.m8n8.x4.shared.b16 {%0,%1,%2,%3}, [%4];"
                 : "=r"(r[0]), "=r"(r[1]), "=r"(r[2]), "=r"(r[3]) : "r"(addr));
}
__device__ __forceinline__ void ldm_x4t(unsigned* r, unsigned addr) {
    asm volatile("ldmatrix.sync.aligned.m8n8.x4.trans.shared.b16 {%0,%1,%2,%3}, [%4];"
                 : "=r"(r[0]), "=r"(r[1]), "=r"(r[2]), "=r"(r[3]) : "r"(addr));
}
__device__ __forceinline__ void mma_bf16(float* d, const unsigned* a, const unsigned* b) {
    asm volatile(
        "mma.sync.aligned.m16n8k16.row.col.f32.bf16.bf16.f32 "
        "{%0,%1,%2,%3}, {%4,%5,%6,%7}, {%8,%9}, {%0,%1,%2,%3};"
        : "+f"(d[0]), "+f"(d[1]), "+f"(d[2]), "+f"(d[3])
        : "r"(a[0]), "r"(a[1]), "r"(a[2]), "r"(a[3]), "r"(b[0]), "r"(b[1]));
}

// ---------------------------------------------------------------------------
// init: g_hbh/g_hbl[0][m][k] = split(h0[m][k]); flags = 0
// ---------------------------------------------------------------------------
__global__ void init_state(const float* __restrict__ h0) {
    int idx = blockIdx.x * 256 + threadIdx.x;   // 0 .. 32767 = m*1024+k
    float v = h0[idx];
    __nv_bfloat16 hi = __float2bfloat16_rn(v);
    __nv_bfloat16 lo = __float2bfloat16_rn(v - __bfloat162float(hi));
    g_hbh[0][idx] = hi;
    g_hbl[0][idx] = lo;
    if (idx < NCTA * 8) g_flags[idx] = 0;
}

// ---------------------------------------------------------------------------
// cvt_split: fp32 -> (bf16 hi, bf16 lo) for x and the 4 gate U matrices.
// ---------------------------------------------------------------------------
#define XN4 ((size_t)16384 * 1024 / 4)
#define UG4 ((size_t)1024 * 1024 / 4)
__global__ __launch_bounds__(256) void cvt_split(
    const float* __restrict__ x,
    const float* __restrict__ Ui, const float* __restrict__ Uf,
    const float* __restrict__ Uc, const float* __restrict__ Uo)
{
    size_t i4 = (size_t)blockIdx.x * 256 + threadIdx.x;
    const float4* src;
    __nv_bfloat162* dh;
    __nv_bfloat162* dl;
    size_t off;
    if (i4 < XN4) {
        src = (const float4*)x;   off = i4;
        dh = (__nv_bfloat162*)g_xh;
        dl = (__nv_bfloat162*)g_xl;
    } else {
        size_t j = i4 - XN4;
        int g = (int)(j >> 18);               // UG4 = 2^18
        size_t o = j & (UG4 - 1);
        const float* Ug = (g == 0) ? Ui : (g == 1) ? Uf : (g == 2) ? Uc : Uo;
        src = (const float4*)Ug;  off = o;
        dh = (__nv_bfloat162*)(g_uh + (size_t)g * 1024 * 1024);
        dl = (__nv_bfloat162*)(g_ul + (size_t)g * 1024 * 1024);
    }
    float4 v = src[off];
    __nv_bfloat16 h0 = __float2bfloat16_rn(v.x);
    __nv_bfloat16 h1 = __float2bfloat16_rn(v.y);
    __nv_bfloat16 h2 = __float2bfloat16_rn(v.z);
    __nv_bfloat16 h3 = __float2bfloat16_rn(v.w);
    __nv_bfloat16 l0 = __float2bfloat16_rn(v.x - __bfloat162float(h0));
    __nv_bfloat16 l1 = __float2bfloat16_rn(v.y - __bfloat162float(h1));
    __nv_bfloat16 l2 = __float2bfloat16_rn(v.z - __bfloat162float(h2));
    __nv_bfloat16 l3 = __float2bfloat16_rn(v.w - __bfloat162float(h3));
    dh[off * 2]     = __halves2bfloat162(h0, h1);
    dh[off * 2 + 1] = __halves2bfloat162(h2, h3);
    dl[off * 2]     = __halves2bfloat162(l0, l1);
    dl[off * 2 + 1] = __halves2bfloat162(l2, l3);
}

// ---------------------------------------------------------------------------
// Phase 1 on tensor cores: g_xu = x @ U_g + b_g via split-bf16 mma.sync.
// (unchanged from R6 winner)
// ---------------------------------------------------------------------------
#define AS_STR 40
#define BS_STR 136

__global__ __launch_bounds__(256, 2) void xu_mma(
    const float* __restrict__ bi, const float* __restrict__ bf,
    const float* __restrict__ bc, const float* __restrict__ bo)
{
    __shared__ __nv_bfloat16 Ash[128 * AS_STR];
    __shared__ __nv_bfloat16 Asl[128 * AS_STR];
    __shared__ __nv_bfloat16 Bsh[32 * BS_STR];
    __shared__ __nv_bfloat16 Bsl[32 * BS_STR];

    const int tid  = threadIdx.x;
    const int wid  = tid >> 5;
    const int lane = tid & 31;
    const int wm   = wid & 3;
    const int wn   = wid >> 2;
    const int m0   = blockIdx.x * 128;
    const int nb   = blockIdx.y;
    const int gate = nb >> 3;
    const int j0   = (nb & 7) * 128;

    const float* bias = (gate == 0) ? bi : (gate == 1) ? bf : (gate == 2) ? bc : bo;
    const __nv_bfloat16* __restrict__ Agh = g_xh;
    const __nv_bfloat16* __restrict__ Agl = g_xl;
    const __nv_bfloat16* __restrict__ Bgh = g_uh + (size_t)gate * 1024 * 1024;
    const __nv_bfloat16* __restrict__ Bgl = g_ul + (size_t)gate * 1024 * 1024;

    float acc[2][8][4];
    #pragma unroll
    for (int ti = 0; ti < 2; ti++)
        #pragma unroll
        for (int tj = 0; tj < 8; tj++)
            #pragma unroll
            for (int q = 0; q < 4; q++) acc[ti][tj][q] = 0.f;

    const int ar = tid >> 2;
    const int ac = tid & 3;
    const int br = tid >> 4;
    const int bc2 = tid & 15;

    const int a_r = (lane & 15);
    const int a_c = (lane >> 4) << 3;
    const int b_k = (lane & 15);
    const int b_n = (lane >> 4) << 3;

    for (int k0 = 0; k0 < DIM; k0 += 32) {
        uint4 avh[2], avl[2], bvh[2], bvl[2];
        #pragma unroll
        for (int u = 0; u < 2; ++u) {
            int row = ar + u * 64;
            avh[u] = __ldg((const uint4*)&Agh[(size_t)(m0 + row) * DIM + k0 + ac * 8]);
            avl[u] = __ldg((const uint4*)&Agl[(size_t)(m0 + row) * DIM + k0 + ac * 8]);
            int krow = br + u * 16;
            bvh[u] = __ldg((const uint4*)&Bgh[(size_t)(k0 + krow) * HID + j0 + bc2 * 8]);
            bvl[u] = __ldg((const uint4*)&Bgl[(size_t)(k0 + krow) * HID + j0 + bc2 * 8]);
        }
        __syncthreads();
        #pragma unroll
        for (int u = 0; u < 2; ++u) {
            int row = ar + u * 64;
            *(uint4*)&Ash[row * AS_STR + ac * 8] = avh[u];
            *(uint4*)&Asl[row * AS_STR + ac * 8] = avl[u];
            int krow = br + u * 16;
            *(uint4*)&Bsh[krow * BS_STR + bc2 * 8] = bvh[u];
            *(uint4*)&Bsl[krow * BS_STR + bc2 * 8] = bvl[u];
        }
        __syncthreads();

        #pragma unroll
        for (int kk = 0; kk < 32; kk += 16) {
            unsigned Ah[2][4], Al[2][4], Bf[4][4];
            #pragma unroll
            for (int ti = 0; ti < 2; ++ti) {
                int row = wm * 32 + ti * 16 + a_r;
                ldm_x4(Ah[ti], smem_u32(&Ash[row * AS_STR + kk + a_c]));
                ldm_x4(Al[ti], smem_u32(&Asl[row * AS_STR + kk + a_c]));
            }
            #pragma unroll
            for (int p = 0; p < 4; ++p) {
                int n = wn * 64 + p * 16 + b_n;
                ldm_x4t(Bf[p], smem_u32(&Bsh[(kk + b_k) * BS_STR + n]));
            }
            #pragma unroll
            for (int ti = 0; ti < 2; ++ti)
                #pragma unroll
                for (int p = 0; p < 4; ++p) {
                    mma_bf16(acc[ti][2 * p],     Ah[ti], &Bf[p][0]);
                    mma_bf16(acc[ti][2 * p + 1], Ah[ti], &Bf[p][2]);
                    mma_bf16(acc[ti][2 * p],     Al[ti], &Bf[p][0]);
                    mma_bf16(acc[ti][2 * p + 1], Al[ti], &Bf[p][2]);
                }
            #pragma unroll
            for (int p = 0; p < 4; ++p) {
                int n = wn * 64 + p * 16 + b_n;
                ldm_x4t(Bf[p], smem_u32(&Bsl[(kk + b_k) * BS_STR + n]));
            }
            #pragma unroll
            for (int ti = 0; ti < 2; ++ti)
                #pragma unroll
                for (int p = 0; p < 4; ++p) {
                    mma_bf16(acc[ti][2 * p],     Ah[ti], &Bf[p][0]);
                    mma_bf16(acc[ti][2 * p + 1], Ah[ti], &Bf[p][2]);
                }
        }
    }

    #pragma unroll
    for (int ti = 0; ti < 2; ++ti) {
        #pragma unroll
        for (int tj = 0; tj < 8; ++tj) {
            int col = j0 + wn * 64 + tj * 8 + (lane & 3) * 2;
            float c0 = __ldg(&bias[col]);
            float c1 = __ldg(&bias[col + 1]);
            int row0 = m0 + wm * 32 + ti * 16 + (lane >> 2);
            int row1 = row0 + 8;
            {
                int b_ = row0 >> 9, s_ = row0 & 511;
                float2* dst = (float2*)&g_xu[(((size_t)s_ * BATCH + b_) * 4 + gate) * HID + col];
                *dst = make_float2(acc[ti][tj][0] + c0, acc[ti][tj][1] + c1);
            }
            {
                int b_ = row1 >> 9, s_ = row1 & 511;
                float2* dst = (float2*)&g_xu[(((size_t)s_ * BATCH + b_) * 4 + gate) * HID + col];
                *dst = make_float2(acc[ti][tj][2] + c0, acc[ti][tj][3] + c1);
            }
        }
    }
}

// ---------------------------------------------------------------------------
// Phase 2: PERSISTENT recurrence on tensor cores (split-bf16 mma.sync).
// 128 CTAs x 256 threads; CTA owns 32 gate-cols (col = j*4+g, j = 8 local).
// V hi/lo resident in smem [1024 k][40-stride col]; h hi/lo published per
// step as [m][k] bf16 globals, staged per 256-k chunk; warp w does k-slice
// [w*32, w*32+32) of each chunk; cross-warp reduce via smem scratch.
// ---------------------------------------------------------------------------
#define VB_STR 40     // V smem row stride (bf16)
#define HB_STR 264    // H smem row stride (bf16)
#define SC_WSTR (32 * 36)   // scratch floats per warp
#define SMEM_BYTES (2 * 1024 * VB_STR * 2 + 8 * SC_WSTR * 4)   // 163840+36864

__global__ __launch_bounds__(NTH, 1) void lstm_persist(
    const float* __restrict__ Vi, const float* __restrict__ Vf,
    const float* __restrict__ Vc, const float* __restrict__ Vo,
    const float* __restrict__ c0,
    float* __restrict__ out_hs,
    float* __restrict__ out_ht,
    float* __restrict__ out_ct)
{
    extern __shared__ char smraw[];
    __nv_bfloat16* Vbh = (__nv_bfloat16*)smraw;            // [1024][VB_STR]
    __nv_bfloat16* Vbl = Vbh + 1024 * VB_STR;
    char* hregion = smraw + (size_t)2 * 1024 * VB_STR * 2;
    __nv_bfloat16* Hsh = (__nv_bfloat16*)hregion;          // [32][HB_STR]
    __nv_bfloat16* Hsl = Hsh + 32 * HB_STR;
    float* scr = (float*)hregion;                          // [8][32][36]

    const int tid  = threadIdx.x;
    const int wid  = tid >> 5;
    const int lane = tid & 31;
    const int jb   = blockIdx.x * 8;

    const int fm  = tid >> 3;            // gating: batch
    const int fj  = tid & 7;             // gating: local column
    const int fjg = jb + fj;

    const int a_r = (lane & 15);
    const int a_c = (lane >> 4) << 3;
    const int b_k = (lane & 15);
    const int b_n = (lane >> 4) << 3;

    // ---- one-time V load + split into smem ----
    for (int e = tid; e < 1024 * 32; e += NTH) {
        int k   = e >> 5;
        int col = e & 31;
        int j   = col >> 2;
        int g   = col & 3;
        const float* Vg = (g == 0) ? Vi : (g == 1) ? Vf : (g == 2) ? Vc : Vo;
        float v = __ldg(&Vg[(size_t)k * HID + jb + j]);
        __nv_bfloat16 hi = __float2bfloat16_rn(v);
        __nv_bfloat16 lo = __float2bfloat16_rn(v - __bfloat162float(hi));
        Vbh[k * VB_STR + col] = hi;
        Vbl[k * VB_STR + col] = lo;
    }
    float cc = __ldg(&c0[fm * HID + fjg]);
    __syncthreads();

    const int sm_m  = tid >> 5;          // staging helper: not used directly
    (void)sm_m;

    for (int s = 0; s < SEQ; ++s) {
        const __nv_bfloat16* __restrict__ hH = g_hbh[s & 1];
        const __nv_bfloat16* __restrict__ hL = g_hbl[s & 1];

        const float* xup = &g_xu[(((size_t)s * BATCH + fm) * 4) * HID + fjg];
        float xi = __ldcs(xup);
        float xf = __ldcs(xup + HID);
        float xg = __ldcs(xup + 2 * HID);
        float xo = __ldcs(xup + 3 * HID);

        float acc[2][4][4];
        #pragma unroll
        for (int ti = 0; ti < 2; ti++)
            #pragma unroll
            for (int nj = 0; nj < 4; nj++)
                #pragma unroll
                for (int q = 0; q < 4; q++) acc[ti][nj][q] = 0.f;

        // prefetch chunk 0: [32 m][256 k] hi+lo (uint4 = 8 bf16)
        uint4 hrH[4], hrL[4];
        #pragma unroll
        for (int r = 0; r < 4; ++r) {
            int idx = r * 256 + tid;      // 0..1023
            int m   = idx >> 5;
            int kq  = idx & 31;
            hrH[r] = __ldcg((const uint4*)&hH[m * HID + kq * 8]);
            hrL[r] = __ldcg((const uint4*)&hL[m * HID + kq * 8]);
        }

        #pragma unroll
        for (int ch = 0; ch < 4; ++ch) {
            __syncthreads();              // previous chunk compute / scratch done
            #pragma unroll
            for (int r = 0; r < 4; ++r) {
                int idx = r * 256 + tid;
                int m   = idx >> 5;
                int kq  = idx & 31;
                *(uint4*)&Hsh[m * HB_STR + kq * 8] = hrH[r];
                *(uint4*)&Hsl[m * HB_STR + kq * 8] = hrL[r];
            }
            __syncthreads();
            if (ch < 3) {
                #pragma unroll
                for (int r = 0; r < 4; ++r) {
                    int idx = r * 256 + tid;
                    int m   = idx >> 5;
                    int kq  = idx & 31;
                    hrH[r] = __ldcg((const uint4*)&hH[m * HID + (ch + 1) * 256 + kq * 8]);
                    hrL[r] = __ldcg((const uint4*)&hL[m * HID + (ch + 1) * 256 + kq * 8]);
                }
            }

            // warp's k-slice within chunk: [wid*32, wid*32+32)
            #pragma unroll
            for (int kk = 0; kk < 32; kk += 16) {
                int kloc = wid * 32 + kk;             // k within chunk
                int kglb = ch * 256 + kloc;           // k within 1024 (for V)
                unsigned Ah[2][4], Al[2][4], Bh[2][4], Bl[2][4];
                #pragma unroll
                for (int ti = 0; ti < 2; ++ti) {
                    int row = ti * 16 + a_r;
                    ldm_x4(Ah[ti], smem_u32(&Hsh[row * HB_STR + kloc + a_c]));
                    ldm_x4(Al[ti], smem_u32(&Hsl[row * HB_STR + kloc + a_c]));
                }
                #pragma unroll
                for (int q = 0; q < 2; ++q) {
                    int n = q * 16 + b_n;
                    ldm_x4t(Bh[q], smem_u32(&Vbh[(kglb + b_k) * VB_STR + n]));
                    ldm_x4t(Bl[q], smem_u32(&Vbl[(kglb + b_k) * VB_STR + n]));
                }
                #pragma unroll
                for (int ti = 0; ti < 2; ++ti)
                    #pragma unroll
                    for (int q = 0; q < 2; ++q) {
                        mma_bf16(acc[ti][2 * q],     Ah[ti], &Bh[q][0]);
                        mma_bf16(acc[ti][2 * q + 1], Ah[ti], &Bh[q][2]);
                        mma_bf16(acc[ti][2 * q],     Al[ti], &Bh[q][0]);
                        mma_bf16(acc[ti][2 * q + 1], Al[ti], &Bh[q][2]);
                        mma_bf16(acc[ti][2 * q],     Ah[ti], &Bl[q][0]);
                        mma_bf16(acc[ti][2 * q + 1], Ah[ti], &Bl[q][2]);
                    }
            }
        }

        // ---- cross-warp reduction via scratch ----
        __syncthreads();                  // last chunk LDSM reads done; reuse H region
        #pragma unroll
        for (int ti = 0; ti < 2; ++ti)
            #pragma unroll
            for (int nj = 0; nj < 4; ++nj)
                #pragma unroll
                for (int u = 0; u < 2; ++u) {
                    int row = ti * 16 + (lane >> 2) + u * 8;
                    int col = nj * 8 + (lane & 3) * 2;
                    *(float2*)&scr[wid * SC_WSTR + row * 36 + col] =
                        make_float2(acc[ti][nj][2 * u], acc[ti][nj][2 * u + 1]);
                }
        __syncthreads();

        float zi = xi, zf = xf, zg = xg, zo = xo;
        #pragma unroll
        for (int w8 = 0; w8 < 8; ++w8) {
            float4 p = *(const float4*)&scr[w8 * SC_WSTR + fm * 36 + fj * 4];
            zi += p.x; zf += p.y; zg += p.z; zo += p.w;
        }

        float ig = sigmoidf_(zi);
        float fg = sigmoidf_(zf);
        float gg = tanhf(zg);
        float og = sigmoidf_(zo);
        cc = fg * cc + ig * gg;
        float h = og * tanhf(cc);

        __nv_bfloat16 hhi = __float2bfloat16_rn(h);
        __nv_bfloat16 hlo = __float2bfloat16_rn(h - __bfloat162float(hhi));
        g_hbh[(s + 1) & 1][fm * HID + fjg] = hhi;
        g_hbl[(s + 1) & 1][fm * HID + fjg] = hlo;
        __stcs(&out_hs[((size_t)fm * SEQ + s) * HID + fjg], h);

        if (s == SEQ - 1) {
            out_ht[fm * HID + fjg] = h;
            out_ct[fm * HID + fjg] = cc;
        } else {
            __syncthreads();              // all h stores issued
            if (tid == 0) {
                asm volatile("st.release.gpu.global.u32 [%0], %1;"
                             :: "l"(&g_flags[blockIdx.x * 8]), "r"((unsigned)(s + 1))
                             : "memory");
            }
            if (wid == 0) {
                unsigned target = (unsigned)(s + 1);
                bool ok;
                do {
                    ok = true;
                    #pragma unroll
                    for (int q = 0; q < 4; ++q) {
                        unsigned v;
                        asm volatile("ld.acquire.gpu.global.u32 %0, [%1];"
                                     : "=r"(v)
                                     : "l"(&g_flags[(lane + 32 * q) * 8]));
                        ok = ok && (v >= target);
                    }
                } while (!__all_sync(0xffffffffu, ok));
            }
            __syncthreads();              // release whole CTA
        }
    }
}

// ---------------------------------------------------------------------------
extern "C" void kernel_launch(void* const* d_in, const int* in_sizes, int n_in,
                              void* d_out, int out_size) {
    const float* x   = (const float*)d_in[0];
    const float* h0  = (const float*)d_in[1];
    const float* c0  = (const float*)d_in[2];
    const float* U_i = (const float*)d_in[3];
    const float* V_i = (const float*)d_in[4];
    const float* b_i = (const float*)d_in[5];
    const float* U_f = (const float*)d_in[6];
    const float* V_f = (const float*)d_in[7];
    const float* b_f = (const float*)d_in[8];
    const float* U_c = (const float*)d_in[9];
    const float* V_c = (const float*)d_in[10];
    const float* b_c = (const float*)d_in[11];
    const float* U_o = (const float*)d_in[12];
    const float* V_o = (const float*)d_in[13];
    const float* b_o = (const float*)d_in[14];

    float* out    = (float*)d_out;
    float* out_hs = out;
    float* out_ht = out + (size_t)BATCH * SEQ * HID;
    float* out_ct = out_ht + (size_t)BATCH * HID;

    static_assert(SMEM_BYTES <= 227000, "smem budget");
    cudaFuncSetAttribute(lstm_persist,
                         cudaFuncAttributeMaxDynamicSharedMemorySize,
                         SMEM_BYTES);

    init_state<<<128, 256>>>(h0);

    size_t total4 = XN4 + 4 * UG4;
    cvt_split<<<(unsigned)(total4 / 256), 256>>>(x, U_i, U_f, U_c, U_o);

    dim3 g1(128, 32);
    xu_mma<<<g1, 256>>>(b_i, b_f, b_c, b_o);

    lstm_persist<<<NCTA, NTH, SMEM_BYTES>>>(
        V_i, V_f, V_c, V_o, c0, out_hs, out_ht, out_ct);
}

// round 9
// speedup vs baseline: 3.7570x; 1.0087x over previous
#include <cuda_runtime.h>
#include <cuda_bf16.h>

#define BATCH 32
#define SEQ   512
#define DIM   1024
#define HID   1024
#define NCTA  128
#define NTH   256

typedef unsigned long long ull;

// ---------------- scratch (device globals; no cudaMalloc allowed) ----------
__device__ float g_xu[(size_t)SEQ * BATCH * 4 * HID];   // [s][b][gate][j]
__device__ unsigned g_flags[NCTA * 8];                  // 32B-strided step counters
__device__ __nv_bfloat16 g_xh[(size_t)16384 * 1024];    // x hi  [m][k]
__device__ __nv_bfloat16 g_xl[(size_t)16384 * 1024];    // x lo
__device__ __nv_bfloat16 g_uh[(size_t)4 * 1024 * 1024]; // U hi  [g][k][n]
__device__ __nv_bfloat16 g_ul[(size_t)4 * 1024 * 1024]; // U lo
__device__ __nv_bfloat16 g_hbh[2][BATCH * HID];         // h hi [par][m][k]
__device__ __nv_bfloat16 g_hbl[2][BATCH * HID];         // h lo [par][m][k]

__device__ __forceinline__ float sigmoidf_(float x) {
    return 1.0f / (1.0f + __expf(-x));
}

// ---------------- tensor-core helpers ---------------------------------------
__device__ __forceinline__ unsigned smem_u32(const void* p) {
    return (unsigned)__cvta_generic_to_shared(p);
}
__device__ __forceinline__ void ldm_x4(unsigned* r, unsigned addr) {
    asm volatile("ldmatrix.sync.aligned.m8n8.x4.shared.b16 {%0,%1,%2,%3}, [%4];"
                 : "=r"(r[0]), "=r"(r[1]), "=r"(r[2]), "=r"(r[3]) : "r"(addr));
}
__device__ __forceinline__ void ldm_x4t(unsigned* r, unsigned addr) {
    asm volatile("ldmatrix.sync.aligned.m8n8.x4.trans.shared.b16 {%0,%1,%2,%3}, [%4];"
                 : "=r"(r[0]), "=r"(r[1]), "=r"(r[2]), "=r"(r[3]) : "r"(addr));
}
__device__ __forceinline__ void mma_bf16(float* d, const unsigned* a, const unsigned* b) {
    asm volatile(
        "mma.sync.aligned.m16n8k16.row.col.f32.bf16.bf16.f32 "
        "{%0,%1,%2,%3}, {%4,%5,%6,%7}, {%8,%9}, {%0,%1,%2,%3};"
        : "+f"(d[0]), "+f"(d[1]), "+f"(d[2]), "+f"(d[3])
        : "r"(a[0]), "r"(a[1]), "r"(a[2]), "r"(a[3]), "r"(b[0]), "r"(b[1]));
}

// ---------------------------------------------------------------------------
// init: g_hbh/g_hbl[0][m][k] = split(h0[m][k]); flags = 0
// ---------------------------------------------------------------------------
__global__ void init_state(const float* __restrict__ h0) {
    int idx = blockIdx.x * 256 + threadIdx.x;   // 0 .. 32767 = m*1024+k
    float v = h0[idx];
    __nv_bfloat16 hi = __float2bfloat16_rn(v);
    __nv_bfloat16 lo = __float2bfloat16_rn(v - __bfloat162float(hi));
    g_hbh[0][idx] = hi;
    g_hbl[0][idx] = lo;
    if (idx < NCTA * 8) g_flags[idx] = 0;
}

// ---------------------------------------------------------------------------
// cvt_split: fp32 -> (bf16 hi, bf16 lo) for x and the 4 gate U matrices.
// ---------------------------------------------------------------------------
#define XN4 ((size_t)16384 * 1024 / 4)
#define UG4 ((size_t)1024 * 1024 / 4)
__global__ __launch_bounds__(256) void cvt_split(
    const float* __restrict__ x,
    const float* __restrict__ Ui, const float* __restrict__ Uf,
    const float* __restrict__ Uc, const float* __restrict__ Uo)
{
    size_t i4 = (size_t)blockIdx.x * 256 + threadIdx.x;
    const float4* src;
    __nv_bfloat162* dh;
    __nv_bfloat162* dl;
    size_t off;
    if (i4 < XN4) {
        src = (const float4*)x;   off = i4;
        dh = (__nv_bfloat162*)g_xh;
        dl = (__nv_bfloat162*)g_xl;
    } else {
        size_t j = i4 - XN4;
        int g = (int)(j >> 18);               // UG4 = 2^18
        size_t o = j & (UG4 - 1);
        const float* Ug = (g == 0) ? Ui : (g == 1) ? Uf : (g == 2) ? Uc : Uo;
        src = (const float4*)Ug;  off = o;
        dh = (__nv_bfloat162*)(g_uh + (size_t)g * 1024 * 1024);
        dl = (__nv_bfloat162*)(g_ul + (size_t)g * 1024 * 1024);
    }
    float4 v = src[off];
    __nv_bfloat16 h0 = __float2bfloat16_rn(v.x);
    __nv_bfloat16 h1 = __float2bfloat16_rn(v.y);
    __nv_bfloat16 h2 = __float2bfloat16_rn(v.z);
    __nv_bfloat16 h3 = __float2bfloat16_rn(v.w);
    __nv_bfloat16 l0 = __float2bfloat16_rn(v.x - __bfloat162float(h0));
    __nv_bfloat16 l1 = __float2bfloat16_rn(v.y - __bfloat162float(h1));
    __nv_bfloat16 l2 = __float2bfloat16_rn(v.z - __bfloat162float(h2));
    __nv_bfloat16 l3 = __float2bfloat16_rn(v.w - __bfloat162float(h3));
    dh[off * 2]     = __halves2bfloat162(h0, h1);
    dh[off * 2 + 1] = __halves2bfloat162(h2, h3);
    dl[off * 2]     = __halves2bfloat162(l0, l1);
    dl[off * 2 + 1] = __halves2bfloat162(l2, l3);
}

// ---------------------------------------------------------------------------
// Phase 1 on tensor cores: g_xu = x @ U_g + b_g via split-bf16 mma.sync.
// (unchanged from R6 winner)
// ---------------------------------------------------------------------------
#define AS_STR 40
#define BS_STR 136

__global__ __launch_bounds__(256, 2) void xu_mma(
    const float* __restrict__ bi, const float* __restrict__ bf,
    const float* __restrict__ bc, const float* __restrict__ bo)
{
    __shared__ __nv_bfloat16 Ash[128 * AS_STR];
    __shared__ __nv_bfloat16 Asl[128 * AS_STR];
    __shared__ __nv_bfloat16 Bsh[32 * BS_STR];
    __shared__ __nv_bfloat16 Bsl[32 * BS_STR];

    const int tid  = threadIdx.x;
    const int wid  = tid >> 5;
    const int lane = tid & 31;
    const int wm   = wid & 3;
    const int wn   = wid >> 2;
    const int m0   = blockIdx.x * 128;
    const int nb   = blockIdx.y;
    const int gate = nb >> 3;
    const int j0   = (nb & 7) * 128;

    const float* bias = (gate == 0) ? bi : (gate == 1) ? bf : (gate == 2) ? bc : bo;
    const __nv_bfloat16* __restrict__ Agh = g_xh;
    const __nv_bfloat16* __restrict__ Agl = g_xl;
    const __nv_bfloat16* __restrict__ Bgh = g_uh + (size_t)gate * 1024 * 1024;
    const __nv_bfloat16* __restrict__ Bgl = g_ul + (size_t)gate * 1024 * 1024;

    float acc[2][8][4];
    #pragma unroll
    for (int ti = 0; ti < 2; ti++)
        #pragma unroll
        for (int tj = 0; tj < 8; tj++)
            #pragma unroll
            for (int q = 0; q < 4; q++) acc[ti][tj][q] = 0.f;

    const int ar = tid >> 2;
    const int ac = tid & 3;
    const int br = tid >> 4;
    const int bc2 = tid & 15;

    const int a_r = (lane & 15);
    const int a_c = (lane >> 4) << 3;
    const int b_k = (lane & 15);
    const int b_n = (lane >> 4) << 3;

    for (int k0 = 0; k0 < DIM; k0 += 32) {
        uint4 avh[2], avl[2], bvh[2], bvl[2];
        #pragma unroll
        for (int u = 0; u < 2; ++u) {
            int row = ar + u * 64;
            avh[u] = __ldg((const uint4*)&Agh[(size_t)(m0 + row) * DIM + k0 + ac * 8]);
            avl[u] = __ldg((const uint4*)&Agl[(size_t)(m0 + row) * DIM + k0 + ac * 8]);
            int krow = br + u * 16;
            bvh[u] = __ldg((const uint4*)&Bgh[(size_t)(k0 + krow) * HID + j0 + bc2 * 8]);
            bvl[u] = __ldg((const uint4*)&Bgl[(size_t)(k0 + krow) * HID + j0 + bc2 * 8]);
        }
        __syncthreads();
        #pragma unroll
        for (int u = 0; u < 2; ++u) {
            int row = ar + u * 64;
            *(uint4*)&Ash[row * AS_STR + ac * 8] = avh[u];
            *(uint4*)&Asl[row * AS_STR + ac * 8] = avl[u];
            int krow = br + u * 16;
            *(uint4*)&Bsh[krow * BS_STR + bc2 * 8] = bvh[u];
            *(uint4*)&Bsl[krow * BS_STR + bc2 * 8] = bvl[u];
        }
        __syncthreads();

        #pragma unroll
        for (int kk = 0; kk < 32; kk += 16) {
            unsigned Ah[2][4], Al[2][4], Bf[4][4];
            #pragma unroll
            for (int ti = 0; ti < 2; ++ti) {
                int row = wm * 32 + ti * 16 + a_r;
                ldm_x4(Ah[ti], smem_u32(&Ash[row * AS_STR + kk + a_c]));
                ldm_x4(Al[ti], smem_u32(&Asl[row * AS_STR + kk + a_c]));
            }
            #pragma unroll
            for (int p = 0; p < 4; ++p) {
                int n = wn * 64 + p * 16 + b_n;
                ldm_x4t(Bf[p], smem_u32(&Bsh[(kk + b_k) * BS_STR + n]));
            }
            #pragma unroll
            for (int ti = 0; ti < 2; ++ti)
                #pragma unroll
                for (int p = 0; p < 4; ++p) {
                    mma_bf16(acc[ti][2 * p],     Ah[ti], &Bf[p][0]);
                    mma_bf16(acc[ti][2 * p + 1], Ah[ti], &Bf[p][2]);
                    mma_bf16(acc[ti][2 * p],     Al[ti], &Bf[p][0]);
                    mma_bf16(acc[ti][2 * p + 1], Al[ti], &Bf[p][2]);
                }
            #pragma unroll
            for (int p = 0; p < 4; ++p) {
                int n = wn * 64 + p * 16 + b_n;
                ldm_x4t(Bf[p], smem_u32(&Bsl[(kk + b_k) * BS_STR + n]));
            }
            #pragma unroll
            for (int ti = 0; ti < 2; ++ti)
                #pragma unroll
                for (int p = 0; p < 4; ++p) {
                    mma_bf16(acc[ti][2 * p],     Ah[ti], &Bf[p][0]);
                    mma_bf16(acc[ti][2 * p + 1], Ah[ti], &Bf[p][2]);
                }
        }
    }

    #pragma unroll
    for (int ti = 0; ti < 2; ++ti) {
        #pragma unroll
        for (int tj = 0; tj < 8; ++tj) {
            int col = j0 + wn * 64 + tj * 8 + (lane & 3) * 2;
            float c0 = __ldg(&bias[col]);
            float c1 = __ldg(&bias[col + 1]);
            int row0 = m0 + wm * 32 + ti * 16 + (lane >> 2);
            int row1 = row0 + 8;
            {
                int b_ = row0 >> 9, s_ = row0 & 511;
                float2* dst = (float2*)&g_xu[(((size_t)s_ * BATCH + b_) * 4 + gate) * HID + col];
                *dst = make_float2(acc[ti][tj][0] + c0, acc[ti][tj][1] + c1);
            }
            {
                int b_ = row1 >> 9, s_ = row1 & 511;
                float2* dst = (float2*)&g_xu[(((size_t)s_ * BATCH + b_) * 4 + gate) * HID + col];
                *dst = make_float2(acc[ti][tj][2] + c0, acc[ti][tj][3] + c1);
            }
        }
    }
}

// ---------------------------------------------------------------------------
// Phase 2: PERSISTENT recurrence, split-bf16 mma (R7 geometry: VB_STR=40,
// 4 chunks of 256 k) + distributed flag sync. Each staging thread waits only
// on the 4 producer CTAs owning its k-slices (one per chunk); the CTA-wide
// join happens at the first staging __syncthreads. Flag post precedes the
// out_hs streaming store.
// ---------------------------------------------------------------------------
#define VB_STR 40     // V smem row stride (bf16) — multiple of 8 (ldmatrix 16B)
#define HB_STR 264    // H smem row stride (bf16)
#define SC_WSTR (32 * 36)   // scratch floats per warp
#define SMEM_BYTES (2 * 1024 * VB_STR * 2 + 8 * SC_WSTR * 4)   // 163840+36864

__global__ __launch_bounds__(NTH, 1) void lstm_persist(
    const float* __restrict__ Vi, const float* __restrict__ Vf,
    const float* __restrict__ Vc, const float* __restrict__ Vo,
    const float* __restrict__ c0,
    float* __restrict__ out_hs,
    float* __restrict__ out_ht,
    float* __restrict__ out_ct)
{
    extern __shared__ char smraw[];
    __nv_bfloat16* Vbh = (__nv_bfloat16*)smraw;            // [1024][VB_STR]
    __nv_bfloat16* Vbl = Vbh + 1024 * VB_STR;
    char* hregion = smraw + (size_t)2 * 1024 * VB_STR * 2;
    __nv_bfloat16* Hsh = (__nv_bfloat16*)hregion;          // [32][HB_STR]
    __nv_bfloat16* Hsl = Hsh + 32 * HB_STR;
    float* scr = (float*)hregion;                          // [8][32][36] alias

    const int tid  = threadIdx.x;
    const int wid  = tid >> 5;
    const int lane = tid & 31;
    const int jb   = blockIdx.x * 8;

    const int fm  = tid >> 3;            // gating: batch
    const int fj  = tid & 7;             // gating: local column
    const int fjg = jb + fj;

    const int a_r = (lane & 15);
    const int a_c = (lane >> 4) << 3;
    const int b_k = (lane & 15);
    const int b_n = (lane >> 4) << 3;

    // producer flags this thread depends on: chunk ch slice kq -> CTA ch*32+kq
    const int kq5 = tid & 31;
    const unsigned* fl0 = &g_flags[(0 * 32 + kq5) * 8];
    const unsigned* fl1 = &g_flags[(1 * 32 + kq5) * 8];
    const unsigned* fl2 = &g_flags[(2 * 32 + kq5) * 8];
    const unsigned* fl3 = &g_flags[(3 * 32 + kq5) * 8];

    // ---- one-time V load + split into smem ----
    for (int e = tid; e < 1024 * 32; e += NTH) {
        int k   = e >> 5;
        int col = e & 31;
        int j   = col >> 2;
        int g   = col & 3;
        const float* Vg = (g == 0) ? Vi : (g == 1) ? Vf : (g == 2) ? Vc : Vo;
        float v = __ldg(&Vg[(size_t)k * HID + jb + j]);
        __nv_bfloat16 hi = __float2bfloat16_rn(v);
        __nv_bfloat16 lo = __float2bfloat16_rn(v - __bfloat162float(hi));
        Vbh[k * VB_STR + col] = hi;
        Vbl[k * VB_STR + col] = lo;
    }
    float cc = __ldg(&c0[fm * HID + fjg]);
    __syncthreads();

    for (int s = 0; s < SEQ; ++s) {
        const __nv_bfloat16* __restrict__ hH = g_hbh[s & 1];
        const __nv_bfloat16* __restrict__ hL = g_hbl[s & 1];

        const float* xup = &g_xu[(((size_t)s * BATCH + fm) * 4) * HID + fjg];
        float xi = __ldcs(xup);
        float xf = __ldcs(xup + HID);
        float xg = __ldcs(xup + 2 * HID);
        float xo = __ldcs(xup + 3 * HID);

        // ---- distributed wait: only this thread's 4 producers ----
        {
            unsigned tgt = (unsigned)s;
            unsigned v0, v1, v2, v3;
            do {
                asm volatile("ld.acquire.gpu.global.u32 %0, [%1];" : "=r"(v0) : "l"(fl0));
                asm volatile("ld.acquire.gpu.global.u32 %0, [%1];" : "=r"(v1) : "l"(fl1));
                asm volatile("ld.acquire.gpu.global.u32 %0, [%1];" : "=r"(v2) : "l"(fl2));
                asm volatile("ld.acquire.gpu.global.u32 %0, [%1];" : "=r"(v3) : "l"(fl3));
            } while (v0 < tgt || v1 < tgt || v2 < tgt || v3 < tgt);
        }

        float acc[2][4][4];
        #pragma unroll
        for (int ti = 0; ti < 2; ti++)
            #pragma unroll
            for (int nj = 0; nj < 4; nj++)
                #pragma unroll
                for (int q = 0; q < 4; q++) acc[ti][nj][q] = 0.f;

        // prefetch chunk 0: [32 m][256 k] hi+lo (uint4 = 8 bf16)
        uint4 hrH[4], hrL[4];
        #pragma unroll
        for (int r = 0; r < 4; ++r) {
            int idx = r * 256 + tid;      // 0..1023
            int m   = idx >> 5;
            int kq  = idx & 31;
            hrH[r] = __ldcg((const uint4*)&hH[m * HID + kq * 8]);
            hrL[r] = __ldcg((const uint4*)&hL[m * HID + kq * 8]);
        }

        #pragma unroll
        for (int ch = 0; ch < 4; ++ch) {
            __syncthreads();              // previous chunk compute / scratch done
            #pragma unroll
            for (int r = 0; r < 4; ++r) {
                int idx = r * 256 + tid;
                int m   = idx >> 5;
                int kq  = idx & 31;
                *(uint4*)&Hsh[m * HB_STR + kq * 8] = hrH[r];
                *(uint4*)&Hsl[m * HB_STR + kq * 8] = hrL[r];
            }
            __syncthreads();
            if (ch < 3) {
                #pragma unroll
                for (int r = 0; r < 4; ++r) {
                    int idx = r * 256 + tid;
                    int m   = idx >> 5;
                    int kq  = idx & 31;
                    hrH[r] = __ldcg((const uint4*)&hH[m * HID + (ch + 1) * 256 + kq * 8]);
                    hrL[r] = __ldcg((const uint4*)&hL[m * HID + (ch + 1) * 256 + kq * 8]);
                }
            }

            // warp's k-slice within chunk: [wid*32, wid*32+32)
            #pragma unroll
            for (int kk = 0; kk < 32; kk += 16) {
                int kloc = wid * 32 + kk;             // k within chunk
                int kglb = ch * 256 + kloc;           // k within 1024 (for V)
                unsigned Ah[2][4], Al[2][4], Bh[2][4], Bl[2][4];
                #pragma unroll
                for (int ti = 0; ti < 2; ++ti) {
                    int row = ti * 16 + a_r;
                    ldm_x4(Ah[ti], smem_u32(&Hsh[row * HB_STR + kloc + a_c]));
                    ldm_x4(Al[ti], smem_u32(&Hsl[row * HB_STR + kloc + a_c]));
                }
                #pragma unroll
                for (int q = 0; q < 2; ++q) {
                    int n = q * 16 + b_n;
                    ldm_x4t(Bh[q], smem_u32(&Vbh[(kglb + b_k) * VB_STR + n]));
                    ldm_x4t(Bl[q], smem_u32(&Vbl[(kglb + b_k) * VB_STR + n]));
                }
                #pragma unroll
                for (int ti = 0; ti < 2; ++ti)
                    #pragma unroll
                    for (int q = 0; q < 2; ++q) {
                        mma_bf16(acc[ti][2 * q],     Ah[ti], &Bh[q][0]);
                        mma_bf16(acc[ti][2 * q + 1], Ah[ti], &Bh[q][2]);
                        mma_bf16(acc[ti][2 * q],     Al[ti], &Bh[q][0]);
                        mma_bf16(acc[ti][2 * q + 1], Al[ti], &Bh[q][2]);
                        mma_bf16(acc[ti][2 * q],     Ah[ti], &Bl[q][0]);
                        mma_bf16(acc[ti][2 * q + 1], Ah[ti], &Bl[q][2]);
                    }
            }
        }

        // ---- cross-warp reduction via scratch (aliases H region) ----
        __syncthreads();
        #pragma unroll
        for (int ti = 0; ti < 2; ++ti)
            #pragma unroll
            for (int nj = 0; nj < 4; ++nj)
                #pragma unroll
                for (int u = 0; u < 2; ++u) {
                    int row = ti * 16 + (lane >> 2) + u * 8;
                    int col = nj * 8 + (lane & 3) * 2;
                    *(float2*)&scr[wid * SC_WSTR + row * 36 + col] =
                        make_float2(acc[ti][nj][2 * u], acc[ti][nj][2 * u + 1]);
                }
        __syncthreads();

        float zi = xi, zf = xf, zg = xg, zo = xo;
        #pragma unroll
        for (int w8 = 0; w8 < 8; ++w8) {
            float4 p = *(const float4*)&scr[w8 * SC_WSTR + fm * 36 + fj * 4];
            zi += p.x; zf += p.y; zg += p.z; zo += p.w;
        }

        float ig = sigmoidf_(zi);
        float fg = sigmoidf_(zf);
        float gg = tanhf(zg);
        float og = sigmoidf_(zo);
        cc = fg * cc + ig * gg;
        float h = og * tanhf(cc);

        __nv_bfloat16 hhi = __float2bfloat16_rn(h);
        __nv_bfloat16 hlo = __float2bfloat16_rn(h - __bfloat162float(hhi));
        g_hbh[(s + 1) & 1][fm * HID + fjg] = hhi;
        g_hbl[(s + 1) & 1][fm * HID + fjg] = hlo;

        __syncthreads();                  // all h stores issued (CTA-wide)
        if (tid == 0) {
            asm volatile("st.release.gpu.global.u32 [%0], %1;"
                         :: "l"(&g_flags[blockIdx.x * 8]), "r"((unsigned)(s + 1))
                         : "memory");
        }

        // streaming output store AFTER the flag post (off the critical path)
        __stcs(&out_hs[((size_t)fm * SEQ + s) * HID + fjg], h);

        if (s == SEQ - 1) {
            out_ht[fm * HID + fjg] = h;
            out_ct[fm * HID + fjg] = cc;
        }
    }
}

// ---------------------------------------------------------------------------
extern "C" void kernel_launch(void* const* d_in, const int* in_sizes, int n_in,
                              void* d_out, int out_size) {
    const float* x   = (const float*)d_in[0];
    const float* h0  = (const float*)d_in[1];
    const float* c0  = (const float*)d_in[2];
    const float* U_i = (const float*)d_in[3];
    const float* V_i = (const float*)d_in[4];
    const float* b_i = (const float*)d_in[5];
    const float* U_f = (const float*)d_in[6];
    const float* V_f = (const float*)d_in[7];
    const float* b_f = (const float*)d_in[8];
    const float* U_c = (const float*)d_in[9];
    const float* V_c = (const float*)d_in[10];
    const float* b_c = (const float*)d_in[11];
    const float* U_o = (const float*)d_in[12];
    const float* V_o = (const float*)d_in[13];
    const float* b_o = (const float*)d_in[14];

    float* out    = (float*)d_out;
    float* out_hs = out;
    float* out_ht = out + (size_t)BATCH * SEQ * HID;
    float* out_ct = out_ht + (size_t)BATCH * HID;

    static_assert(SMEM_BYTES <= 227000, "smem budget");
    cudaFuncSetAttribute(lstm_persist,
                         cudaFuncAttributeMaxDynamicSharedMemorySize,
                         SMEM_BYTES);

    init_state<<<128, 256>>>(h0);

    size_t total4 = XN4 + 4 * UG4;
    cvt_split<<<(unsigned)(total4 / 256), 256>>>(x, U_i, U_f, U_c, U_o);

    dim3 g1(128, 32);
    xu_mma<<<g1, 256>>>(b_i, b_f, b_c, b_o);

    lstm_persist<<<NCTA, NTH, SMEM_BYTES>>>(
        V_i, V_f, V_c, V_o, c0, out_hs, out_ht, out_ct);
}